// round 5
// baseline (speedup 1.0000x reference)
#include <cuda_runtime.h>
#include <cuda_bf16.h>
#include <math_constants.h>
#include <cstdint>

// Problem constants
#define SDIM 1024
#define BDIM 4
#define EDIM 256
#define HDIM 8
#define DDIM 32

// d_out layout: out_rgb [S,B,E], out_dpt [S,B,E], shared_rgb [B,H,S,S], shared_dpt [B,H,S,S]
#define OFF_OUT_RGB  0
#define OFF_OUT_DPT  (SDIM*BDIM*EDIM)              // 1048576
#define OFF_SHARED   (2*SDIM*BDIM*EDIM)            // 2097152
#define BHSS         ((size_t)BDIM*HDIM*SDIM*SDIM) // 33554432

#define SCALE 0.17677669529663687f   // 1/sqrt(32)

#define M_TILE 16
#define SSTRIDE 1028                   // score row stride in floats (bank-friendly: 1028%32=4)
#define FUSED_SMEM (2 * M_TILE * SSTRIDE * 4)   // 131584 bytes

// Scratch: qkv heads for 6 projections (2 streams x q/k/v), layout [proj][b][h][s][d]
__device__ float g_qkv[6 * BDIM * HDIM * SDIM * DDIM];   // 25 MB
// Attention output concatenated per stream: [st][b][s][e]
__device__ float g_ocat[2 * BDIM * SDIM * EDIM];         // 8 MB

// ---------------------------------------------------------------------------
// tf32 helpers (mma.sync m16n8k8, fp32 accum)
// ---------------------------------------------------------------------------
__device__ __forceinline__ uint32_t f2tf(float f) {
    uint32_t u;
    asm("cvt.rna.tf32.f32 %0, %1;" : "=r"(u) : "f"(f));
    return u;
}

__device__ __forceinline__ void mma_tf32(float* d, const uint32_t* a, const uint32_t* b) {
    asm volatile(
        "mma.sync.aligned.m16n8k8.row.col.f32.tf32.tf32.f32 "
        "{%0,%1,%2,%3}, {%4,%5,%6,%7}, {%8,%9}, {%0,%1,%2,%3};"
        : "+f"(d[0]), "+f"(d[1]), "+f"(d[2]), "+f"(d[3])
        : "r"(a[0]), "r"(a[1]), "r"(a[2]), "r"(a[3]),
          "r"(b[0]), "r"(b[1]));
}

// ---------------------------------------------------------------------------
// Kernel 1: batched QKV projection (fp32). grid.z = proj id 0..5.
// ---------------------------------------------------------------------------
struct ProjArgs {
    const float* x[6];
    const float* w[2];
    const float* b[2];
};

__global__ __launch_bounds__(256) void proj_kernel(ProjArgs args)
{
    __shared__ float As[16][64];   // [k][m]
    __shared__ float Bs[16][64];   // [k][n]
    const int proj = blockIdx.z;
    const int st = proj / 3;
    const int wsel = proj - st * 3;
    const float* x = args.x[proj];
    const float* W = args.w[st] + (size_t)wsel * 256 * 256;
    const float* bias = args.b[st] + wsel * 256;

    const int bm = blockIdx.y * 64;
    const int bn = blockIdx.x * 64;
    const int tid = threadIdx.x;
    const int tx = tid & 15;        // n dir
    const int ty = tid >> 4;        // m dir

    float acc[4][4] = {};
    const int lrow = tid >> 2;
    const int lcol = (tid & 3) * 4;

    for (int k0 = 0; k0 < 256; k0 += 16) {
        float4 va = *reinterpret_cast<const float4*>(x + (size_t)(bm + lrow) * 256 + k0 + lcol);
        float4 vb = *reinterpret_cast<const float4*>(W + (size_t)(bn + lrow) * 256 + k0 + lcol);
        As[lcol + 0][lrow] = va.x; As[lcol + 1][lrow] = va.y;
        As[lcol + 2][lrow] = va.z; As[lcol + 3][lrow] = va.w;
        Bs[lcol + 0][lrow] = vb.x; Bs[lcol + 1][lrow] = vb.y;
        Bs[lcol + 2][lrow] = vb.z; Bs[lcol + 3][lrow] = vb.w;
        __syncthreads();
#pragma unroll
        for (int kk = 0; kk < 16; kk++) {
            float a[4], b[4];
#pragma unroll
            for (int i = 0; i < 4; i++) a[i] = As[kk][ty * 4 + i];
#pragma unroll
            for (int j = 0; j < 4; j++) b[j] = Bs[kk][tx * 4 + j];
#pragma unroll
            for (int i = 0; i < 4; i++)
#pragma unroll
                for (int j = 0; j < 4; j++) acc[i][j] += a[i] * b[j];
        }
        __syncthreads();
    }

#pragma unroll
    for (int i = 0; i < 4; i++) {
        const int m = bm + ty * 4 + i;
        const int s = m >> 2;       // rows are s*B+b
        const int b = m & 3;
#pragma unroll
        for (int j = 0; j < 4; j++) {
            const int n = bn + tx * 4 + j;
            const int h = n >> 5;
            const int d = n & 31;
            g_qkv[(((size_t)(proj * 4 + b) * 8 + h) * 1024 + s) * 32 + d] = acc[i][j] + bias[n];
        }
    }
}

// ---------------------------------------------------------------------------
// Kernel 2 (FUSED): scores (tf32 mma) + softmax + blend + PV (tf32 mma).
// Block = one (b,h), one 16-query tile, BOTH streams. 512 threads (16 warps).
// Dynamic smem: Sc[2][16][SSTRIDE] fp32 score rows (reused for PV partials).
// Blended probs (required output) written once with streaming stores.
// ---------------------------------------------------------------------------
__global__ __launch_bounds__(512) void fused_attn_kernel(
    float* __restrict__ dout, const unsigned char* __restrict__ mask,
    const float* __restrict__ alpha_p, const float* __restrict__ beta_p)
{
    extern __shared__ float Sc[];   // [2][16][SSTRIDE]
    const int bh = blockIdx.y;      // b*8+h
    const int b = bh >> 3;
    const int h = bh & 7;
    const int bq = blockIdx.x * M_TILE;

    const int tid = threadIdx.x;
    const int wid = tid >> 5;       // 0..15
    const int lane = tid & 31;
    const int gid = lane >> 2;      // 0..7
    const int tig = lane & 3;       // 0..3

    const float* Qb[2], * Kb[2], * Vb[2];
#pragma unroll
    for (int st = 0; st < 2; st++) {
        Qb[st] = g_qkv + ((size_t)(st * 3 + 0) * 32 + bh) * (SDIM * DDIM);
        Kb[st] = g_qkv + ((size_t)(st * 3 + 1) * 32 + bh) * (SDIM * DDIM);
        Vb[st] = g_qkv + ((size_t)(st * 3 + 2) * 32 + bh) * (SDIM * DDIM);
    }

    // ---- load Q A-fragments (held in registers for whole QK phase) ----
    uint32_t qf[2][4][4];
#pragma unroll
    for (int st = 0; st < 2; st++)
#pragma unroll
        for (int ks = 0; ks < 4; ks++) {
            const float* q = Qb[st];
            qf[st][ks][0] = f2tf(q[(size_t)(bq + gid)     * 32 + ks * 8 + tig]);
            qf[st][ks][1] = f2tf(q[(size_t)(bq + gid + 8) * 32 + ks * 8 + tig]);
            qf[st][ks][2] = f2tf(q[(size_t)(bq + gid)     * 32 + ks * 8 + tig + 4]);
            qf[st][ks][3] = f2tf(q[(size_t)(bq + gid + 8) * 32 + ks * 8 + tig + 4]);
        }

    // ---- QK^T: each warp owns 64 key columns ----
    const int kbase = wid * 64;
#pragma unroll
    for (int st = 0; st < 2; st++) {
        float* S = Sc + st * M_TILE * SSTRIDE;
        const float* K = Kb[st];
#pragma unroll
        for (int j = 0; j < 8; j++) {
            const int c0 = kbase + j * 8;
            float acc[4] = {};
#pragma unroll
            for (int ks = 0; ks < 4; ks++) {
                uint32_t bf[2];
                bf[0] = f2tf(K[(size_t)(c0 + gid) * 32 + ks * 8 + tig]);
                bf[1] = f2tf(K[(size_t)(c0 + gid) * 32 + ks * 8 + tig + 4]);
                mma_tf32(acc, qf[st][ks], bf);
            }
            S[(size_t)gid       * SSTRIDE + c0 + tig * 2]     = acc[0] * SCALE;
            S[(size_t)gid       * SSTRIDE + c0 + tig * 2 + 1] = acc[1] * SCALE;
            S[(size_t)(gid + 8) * SSTRIDE + c0 + tig * 2]     = acc[2] * SCALE;
            S[(size_t)(gid + 8) * SSTRIDE + c0 + tig * 2 + 1] = acc[3] * SCALE;
        }
    }
    __syncthreads();

    // ---- softmax + blend: warp w owns row w (both streams) ----
    const unsigned char* mrow = mask + (size_t)b * SDIM;
    float sums[2];
#pragma unroll
    for (int st = 0; st < 2; st++) {
        float* S = Sc + (st * M_TILE + wid) * SSTRIDE;
        float mx = -CUDART_INF_F;
#pragma unroll 8
        for (int i = 0; i < 32; i++) {
            const int c = lane + i * 32;
            if (!mrow[c]) mx = fmaxf(mx, S[c]);
        }
#pragma unroll
        for (int o = 16; o > 0; o >>= 1)
            mx = fmaxf(mx, __shfl_xor_sync(0xffffffffu, mx, o));
        float sm = 0.f;
#pragma unroll 8
        for (int i = 0; i < 32; i++) {
            const int c = lane + i * 32;
            float e = mrow[c] ? 0.f : __expf(S[c] - mx);
            S[c] = e;
            sm += e;
        }
#pragma unroll
        for (int o = 16; o > 0; o >>= 1)
            sm += __shfl_xor_sync(0xffffffffu, sm, o);
        sums[st] = sm;
    }
    {
        const float inv1 = 1.f / sums[0];
        const float inv2 = 1.f / sums[1];
        const float a = *alpha_p;
        const float bt = *beta_p;
        float* S1 = Sc + (size_t)wid * SSTRIDE;
        float* S2 = Sc + (size_t)(M_TILE + wid) * SSTRIDE;
        float* o1 = dout + OFF_SHARED + ((size_t)bh * SDIM + bq + wid) * SDIM;
        float* o2 = o1 + BHSS;
#pragma unroll 8
        for (int i = 0; i < 32; i++) {
            const int c = lane + i * 32;
            const float p1 = S1[c] * inv1;
            const float p2 = S2[c] * inv2;
            const float b1 = (1.f - a) * p1 + a * p2;
            const float b2 = (1.f - bt) * p2 + bt * p1;
            __stcs(o1 + c, b1);              // streaming: written once, never re-read
            __stcs(o2 + c, b2);
            S1[c] = __uint_as_float(f2tf(b1));   // tf32 bits for PV mma
            S2[c] = __uint_as_float(f2tf(b2));
        }
    }
    __syncthreads();

    // ---- PV: warps 0-7 -> stream0, 8-15 -> stream1; each warp 128 keys ----
    float acc[4][4] = {};
    {
        const int stp = wid >> 3;
        const int kb = (wid & 7) * 128;
        const uint32_t* P = (const uint32_t*)(Sc + (size_t)stp * M_TILE * SSTRIDE);
        const float* V = Vb[stp];
#pragma unroll
        for (int ks = 0; ks < 16; ks++) {
            const int k0 = kb + ks * 8;
            uint32_t a[4];
            a[0] = P[(size_t)gid       * SSTRIDE + k0 + tig];
            a[1] = P[(size_t)(gid + 8) * SSTRIDE + k0 + tig];
            a[2] = P[(size_t)gid       * SSTRIDE + k0 + tig + 4];
            a[3] = P[(size_t)(gid + 8) * SSTRIDE + k0 + tig + 4];
#pragma unroll
            for (int j = 0; j < 4; j++) {
                uint32_t bf[2];
                bf[0] = f2tf(V[(size_t)(k0 + tig)     * 32 + j * 8 + gid]);
                bf[1] = f2tf(V[(size_t)(k0 + tig + 4) * 32 + j * 8 + gid]);
                mma_tf32(acc[j], a, bf);
            }
        }
    }
    __syncthreads();

    // ---- partial reduction through (reused) smem ----
    {
        const int stp = wid >> 3;
        float* pw = Sc + (size_t)((stp * 8 + (wid & 7)) * M_TILE) * 32;
#pragma unroll
        for (int j = 0; j < 4; j++) {
            const int d0 = j * 8 + tig * 2;
            pw[gid * 32 + d0]           = acc[j][0];
            pw[gid * 32 + d0 + 1]       = acc[j][1];
            pw[(gid + 8) * 32 + d0]     = acc[j][2];
            pw[(gid + 8) * 32 + d0 + 1] = acc[j][3];
        }
    }
    __syncthreads();

    for (int idx = tid; idx < 2 * M_TILE * 32; idx += 512) {
        const int st = idx >> 9;
        const int row = (idx >> 5) & 15;
        const int d = idx & 31;
        float s = 0.f;
#pragma unroll
        for (int w = 0; w < 8; w++)
            s += Sc[(size_t)((st * 8 + w) * M_TILE + row) * 32 + d];
        g_ocat[((size_t)(st * 4 + b) * SDIM + bq + row) * EDIM + h * 32 + d] = s;
    }
}

// ---------------------------------------------------------------------------
// Kernel 3: batched output projection (fp32). grid.z = stream 0..1.
// ---------------------------------------------------------------------------
struct OutArgs {
    const float* w[2];
    const float* b[2];
};

__global__ __launch_bounds__(256) void outproj_kernel(OutArgs args, float* __restrict__ dout)
{
    __shared__ float As[16][64];
    __shared__ float Bs[16][64];
    const int st = blockIdx.z;
    const float* W = args.w[st];
    const float* bias = args.b[st];
    float* out = dout + (size_t)st * (SDIM * BDIM * EDIM);

    const int bm = blockIdx.y * 64;
    const int bn = blockIdx.x * 64;
    const int tid = threadIdx.x;
    const int tx = tid & 15;
    const int ty = tid >> 4;
    const float* A = g_ocat + (size_t)st * (BDIM * SDIM * EDIM);

    float acc[4][4] = {};
    const int lrow = tid >> 2;
    const int lcol = (tid & 3) * 4;

    for (int k0 = 0; k0 < 256; k0 += 16) {
        float4 va = *reinterpret_cast<const float4*>(A + (size_t)(bm + lrow) * 256 + k0 + lcol);
        float4 vb = *reinterpret_cast<const float4*>(W + (size_t)(bn + lrow) * 256 + k0 + lcol);
        As[lcol + 0][lrow] = va.x; As[lcol + 1][lrow] = va.y;
        As[lcol + 2][lrow] = va.z; As[lcol + 3][lrow] = va.w;
        Bs[lcol + 0][lrow] = vb.x; Bs[lcol + 1][lrow] = vb.y;
        Bs[lcol + 2][lrow] = vb.z; Bs[lcol + 3][lrow] = vb.w;
        __syncthreads();
#pragma unroll
        for (int kk = 0; kk < 16; kk++) {
            float a[4], b[4];
#pragma unroll
            for (int i = 0; i < 4; i++) a[i] = As[kk][ty * 4 + i];
#pragma unroll
            for (int j = 0; j < 4; j++) b[j] = Bs[kk][tx * 4 + j];
#pragma unroll
            for (int i = 0; i < 4; i++)
#pragma unroll
                for (int j = 0; j < 4; j++) acc[i][j] += a[i] * b[j];
        }
        __syncthreads();
    }

#pragma unroll
    for (int i = 0; i < 4; i++) {
        const int m = bm + ty * 4 + i;     // m = b*1024 + s
        const int b = m >> 10;
        const int s = m & 1023;
#pragma unroll
        for (int j = 0; j < 4; j++) {
            const int n = bn + tx * 4 + j;
            out[(size_t)(s * 4 + b) * 256 + n] = acc[i][j] + bias[n];
        }
    }
}

// ---------------------------------------------------------------------------
extern "C" void kernel_launch(void* const* d_in, const int* in_sizes, int n_in,
                              void* d_out, int out_size)
{
    const unsigned char* mask = (const unsigned char*)d_in[6];
    const float* alpha = (const float*)d_in[15];
    const float* beta  = (const float*)d_in[16];
    float* out = (float*)d_out;

    // allow >48KB dynamic smem for the fused kernel (idempotent)
    cudaFuncSetAttribute(fused_attn_kernel,
                         cudaFuncAttributeMaxDynamicSharedMemorySize, FUSED_SMEM);

    // 1) all six QKV projections in one launch
    ProjArgs pa;
    for (int i = 0; i < 6; i++) pa.x[i] = (const float*)d_in[i];
    pa.w[0] = (const float*)d_in[7];  pa.b[0] = (const float*)d_in[8];
    pa.w[1] = (const float*)d_in[11]; pa.b[1] = (const float*)d_in[12];
    proj_kernel<<<dim3(4, 64, 6), 256>>>(pa);

    // 2) fused scores + softmax + blend + PV
    fused_attn_kernel<<<dim3(SDIM / M_TILE, 32), 512, FUSED_SMEM>>>(out, mask, alpha, beta);

    // 3) both output projections in one launch
    OutArgs oa;
    oa.w[0] = (const float*)d_in[9];  oa.b[0] = (const float*)d_in[10];
    oa.w[1] = (const float*)d_in[13]; oa.b[1] = (const float*)d_in[14];
    outproj_kernel<<<dim3(4, 64, 2), 256>>>(oa, out);
}

// round 6
// speedup vs baseline: 1.5893x; 1.5893x over previous
#include <cuda_runtime.h>
#include <cuda_bf16.h>
#include <math_constants.h>
#include <cstdint>

// Problem constants
#define SDIM 1024
#define BDIM 4
#define EDIM 256
#define HDIM 8
#define DDIM 32

// d_out layout: out_rgb [S,B,E], out_dpt [S,B,E], shared_rgb [B,H,S,S], shared_dpt [B,H,S,S]
#define OFF_OUT_RGB  0
#define OFF_OUT_DPT  (SDIM*BDIM*EDIM)              // 1048576
#define OFF_SHARED   (2*SDIM*BDIM*EDIM)            // 2097152
#define BHSS         ((size_t)BDIM*HDIM*SDIM*SDIM) // 33554432

#define SCALE 0.17677669529663687f   // 1/sqrt(32)

// Scratch: qkv heads for 6 projections (2 streams x q/k/v), layout [proj][b][h][s][d]
__device__ float g_qkv[6 * BDIM * HDIM * SDIM * DDIM];   // 25 MB
// Attention output concatenated per stream: [st][b][s][e]
__device__ float g_ocat[2 * BDIM * SDIM * EDIM];         // 8 MB

// ---------------------------------------------------------------------------
// tf32 helpers (mma.sync m16n8k8, fp32 accum)
// ---------------------------------------------------------------------------
__device__ __forceinline__ uint32_t f2tf(float f) {
    uint32_t u;
    asm("cvt.rna.tf32.f32 %0, %1;" : "=r"(u) : "f"(f));
    return u;
}

__device__ __forceinline__ void mma_tf32(float* d, const uint32_t* a, const uint32_t* b) {
    asm volatile(
        "mma.sync.aligned.m16n8k8.row.col.f32.tf32.tf32.f32 "
        "{%0,%1,%2,%3}, {%4,%5,%6,%7}, {%8,%9}, {%0,%1,%2,%3};"
        : "+f"(d[0]), "+f"(d[1]), "+f"(d[2]), "+f"(d[3])
        : "r"(a[0]), "r"(a[1]), "r"(a[2]), "r"(a[3]),
          "r"(b[0]), "r"(b[1]));
}

// ---------------------------------------------------------------------------
// Kernel 1: batched QKV projection via tf32 mma. grid.z = proj id 0..5.
// y[m=s*4+b, n] = sum_k x[m,k] * W[n,k] + bias[n]
// Block tile 128m x 128n, k-tiles of 32, reg-prefetch pipelined.
// 8 warps: 4 in m x 2 in n; warp tile 32m x 64n.
// Scatter into g_qkv[proj][b][h=n/32][s][d=n%32].
// ---------------------------------------------------------------------------
struct ProjArgs {
    const float* x[6];
    const float* w[2];
    const float* b[2];
};

__global__ __launch_bounds__(256) void proj_tf32_kernel(ProjArgs args)
{
    __shared__ uint32_t As[128][36];
    __shared__ uint32_t Bs[128][36];
    const int proj = blockIdx.z;
    const int st = proj / 3;
    const int wsel = proj - st * 3;
    const float* x = args.x[proj];
    const float* W = args.w[st] + (size_t)wsel * 256 * 256;
    const float* bias = args.b[st] + wsel * 256;

    const int bm = blockIdx.y * 128;
    const int bn = blockIdx.x * 128;
    const int tid = threadIdx.x;
    const int wid = tid >> 5;
    const int lane = tid & 31;
    const int gid = lane >> 2;
    const int tig = lane & 3;
    const int wm = (wid & 3) * 32;
    const int wn = (wid >> 2) * 64;

    // per-thread staging coords: 4 float4 per tensor per tile
    const int sr0 = tid >> 3;            // 0..31, +32*t
    const int sc0 = (tid & 7) * 4;       // 0,4,..28

    float4 pa[4], pb[4];
#pragma unroll
    for (int t = 0; t < 4; t++) {
        pa[t] = *reinterpret_cast<const float4*>(x + (size_t)(bm + sr0 + t * 32) * 256 + sc0);
        pb[t] = *reinterpret_cast<const float4*>(W + (size_t)(bn + sr0 + t * 32) * 256 + sc0);
    }

    float acc[2][8][4] = {};

    for (int kt = 0; kt < 8; kt++) {
        // store prefetched regs to smem
#pragma unroll
        for (int t = 0; t < 4; t++) {
            const int r = sr0 + t * 32;
            As[r][sc0 + 0] = f2tf(pa[t].x); As[r][sc0 + 1] = f2tf(pa[t].y);
            As[r][sc0 + 2] = f2tf(pa[t].z); As[r][sc0 + 3] = f2tf(pa[t].w);
            Bs[r][sc0 + 0] = f2tf(pb[t].x); Bs[r][sc0 + 1] = f2tf(pb[t].y);
            Bs[r][sc0 + 2] = f2tf(pb[t].z); Bs[r][sc0 + 3] = f2tf(pb[t].w);
        }
        __syncthreads();

        // prefetch next tile
        if (kt < 7) {
            const int k0 = (kt + 1) * 32;
#pragma unroll
            for (int t = 0; t < 4; t++) {
                pa[t] = *reinterpret_cast<const float4*>(x + (size_t)(bm + sr0 + t * 32) * 256 + k0 + sc0);
                pb[t] = *reinterpret_cast<const float4*>(W + (size_t)(bn + sr0 + t * 32) * 256 + k0 + sc0);
            }
        }

        // compute on current tile
#pragma unroll
        for (int kc = 0; kc < 4; kc++) {
            const int k8 = kc * 8;
            uint32_t a[2][4], b[8][2];
#pragma unroll
            for (int i = 0; i < 2; i++) {
                const int r = wm + i * 16;
                a[i][0] = As[r + gid][k8 + tig];
                a[i][1] = As[r + gid + 8][k8 + tig];
                a[i][2] = As[r + gid][k8 + tig + 4];
                a[i][3] = As[r + gid + 8][k8 + tig + 4];
            }
#pragma unroll
            for (int j = 0; j < 8; j++) {
                const int c = wn + j * 8;
                b[j][0] = Bs[c + gid][k8 + tig];
                b[j][1] = Bs[c + gid][k8 + tig + 4];
            }
#pragma unroll
            for (int i = 0; i < 2; i++)
#pragma unroll
                for (int j = 0; j < 8; j++)
                    mma_tf32(acc[i][j], a[i], b[j]);
        }
        __syncthreads();
    }

    // epilogue: add bias, scatter to g_qkv
#pragma unroll
    for (int i = 0; i < 2; i++) {
        const int m0 = bm + wm + i * 16 + gid;
        const int s0 = m0 >> 2, b0 = m0 & 3;
        const int m1 = m0 + 8;
        const int s1 = m1 >> 2, b1 = m1 & 3;
#pragma unroll
        for (int j = 0; j < 8; j++) {
            const int c0 = bn + wn + j * 8 + tig * 2;
            const int h = c0 >> 5;
            const int d = c0 & 31;
            const float bv0 = bias[c0], bv1 = bias[c0 + 1];
            float* p0 = &g_qkv[(((size_t)(proj * 4 + b0) * 8 + h) * 1024 + s0) * 32 + d];
            float* p1 = &g_qkv[(((size_t)(proj * 4 + b1) * 8 + h) * 1024 + s1) * 32 + d];
            *reinterpret_cast<float2*>(p0) = make_float2(acc[i][j][0] + bv0, acc[i][j][1] + bv1);
            *reinterpret_cast<float2*>(p1) = make_float2(acc[i][j][2] + bv0, acc[i][j][3] + bv1);
        }
    }
}

// ---------------------------------------------------------------------------
// Kernel 2: scores via tf32 mma. S[b,h,q,k] = scale * sum_d Q[q,d] K[k,d]
// Block tile 128q x 128k, 8 warps (4 in m, 2 in n), warp tile 32x64.
// Raw scores written to shared_* slots of d_out.
// ---------------------------------------------------------------------------
__global__ __launch_bounds__(256) void scores_mma_kernel(float* __restrict__ dout)
{
    __shared__ uint32_t Qs[128][36];
    __shared__ uint32_t Ks[128][36];
    const int z = blockIdx.z;
    const int st = z >> 5;
    const int bh = z & 31;
    const int bq = blockIdx.y * 128;
    const int bk = blockIdx.x * 128;

    const float* Q = g_qkv + ((size_t)(st * 3 + 0) * 32 + bh) * (SDIM * DDIM);
    const float* K = g_qkv + ((size_t)(st * 3 + 1) * 32 + bh) * (SDIM * DDIM);

    const int tid = threadIdx.x;
    for (int i = tid * 4; i < 128 * 32; i += 1024) {
        const int r = i >> 5, c = i & 31;
        float4 q4 = *reinterpret_cast<const float4*>(Q + (size_t)(bq + r) * 32 + c);
        float4 k4 = *reinterpret_cast<const float4*>(K + (size_t)(bk + r) * 32 + c);
        Qs[r][c + 0] = f2tf(q4.x); Qs[r][c + 1] = f2tf(q4.y);
        Qs[r][c + 2] = f2tf(q4.z); Qs[r][c + 3] = f2tf(q4.w);
        Ks[r][c + 0] = f2tf(k4.x); Ks[r][c + 1] = f2tf(k4.y);
        Ks[r][c + 2] = f2tf(k4.z); Ks[r][c + 3] = f2tf(k4.w);
    }
    __syncthreads();

    const int wid = tid >> 5;
    const int lane = tid & 31;
    const int gid = lane >> 2;
    const int tig = lane & 3;
    const int wm = (wid & 3) * 32;
    const int wn = (wid >> 2) * 64;

    float acc[2][8][4] = {};
#pragma unroll
    for (int kc = 0; kc < 4; kc++) {
        const int k0 = kc * 8;
        uint32_t a[2][4], b[8][2];
#pragma unroll
        for (int i = 0; i < 2; i++) {
            const int r = wm + i * 16;
            a[i][0] = Qs[r + gid][k0 + tig];
            a[i][1] = Qs[r + gid + 8][k0 + tig];
            a[i][2] = Qs[r + gid][k0 + tig + 4];
            a[i][3] = Qs[r + gid + 8][k0 + tig + 4];
        }
#pragma unroll
        for (int j = 0; j < 8; j++) {
            const int c = wn + j * 8;
            b[j][0] = Ks[c + gid][k0 + tig];
            b[j][1] = Ks[c + gid][k0 + tig + 4];
        }
#pragma unroll
        for (int i = 0; i < 2; i++)
#pragma unroll
            for (int j = 0; j < 8; j++)
                mma_tf32(acc[i][j], a[i], b[j]);
    }

    float* out = dout + OFF_SHARED + (size_t)st * BHSS + (size_t)bh * SDIM * SDIM;
#pragma unroll
    for (int i = 0; i < 2; i++) {
        const int q0 = bq + wm + i * 16 + gid;
#pragma unroll
        for (int j = 0; j < 8; j++) {
            const int c0 = bk + wn + j * 8 + tig * 2;
            float2 v0 = make_float2(acc[i][j][0] * SCALE, acc[i][j][1] * SCALE);
            float2 v1 = make_float2(acc[i][j][2] * SCALE, acc[i][j][3] * SCALE);
            *reinterpret_cast<float2*>(out + (size_t)q0 * SDIM + c0) = v0;
            *reinterpret_cast<float2*>(out + (size_t)(q0 + 8) * SDIM + c0) = v1;
        }
    }
}

// ---------------------------------------------------------------------------
// Kernel 3: per-row softmax over both streams + blend, in place in d_out.
// ---------------------------------------------------------------------------
__global__ __launch_bounds__(256) void softmax_blend_kernel(
    float* __restrict__ dout, const unsigned char* __restrict__ mask,
    const float* __restrict__ alpha_p, const float* __restrict__ beta_p)
{
    __shared__ float red[2][8];
    const int row = blockIdx.x;           // (b*8+h)*1024 + q
    const int bh = row >> 10;
    const int b = bh >> 3;
    float* pr = dout + OFF_SHARED + (size_t)row * SDIM;
    float* pd = pr + BHSS;
    const unsigned char* mrow = mask + (size_t)b * SDIM;

    const int tid = threadIdx.x;
    const int lane = tid & 31;
    const int warp = tid >> 5;

    float sr[4], sd[4];
    float mr = -CUDART_INF_F, md = -CUDART_INF_F;
#pragma unroll
    for (int j = 0; j < 4; j++) {
        const int k = tid + j * 256;
        const bool m = mrow[k];
        sr[j] = m ? -CUDART_INF_F : pr[k];
        sd[j] = m ? -CUDART_INF_F : pd[k];
        mr = fmaxf(mr, sr[j]);
        md = fmaxf(md, sd[j]);
    }
#pragma unroll
    for (int o = 16; o > 0; o >>= 1) {
        mr = fmaxf(mr, __shfl_xor_sync(0xffffffffu, mr, o));
        md = fmaxf(md, __shfl_xor_sync(0xffffffffu, md, o));
    }
    if (lane == 0) { red[0][warp] = mr; red[1][warp] = md; }
    __syncthreads();
    mr = red[0][0]; md = red[1][0];
#pragma unroll
    for (int w = 1; w < 8; w++) { mr = fmaxf(mr, red[0][w]); md = fmaxf(md, red[1][w]); }
    __syncthreads();

    float er[4], ed[4];
    float s1 = 0.f, s2 = 0.f;
#pragma unroll
    for (int j = 0; j < 4; j++) {
        er[j] = __expf(sr[j] - mr);
        ed[j] = __expf(sd[j] - md);
        s1 += er[j]; s2 += ed[j];
    }
#pragma unroll
    for (int o = 16; o > 0; o >>= 1) {
        s1 += __shfl_xor_sync(0xffffffffu, s1, o);
        s2 += __shfl_xor_sync(0xffffffffu, s2, o);
    }
    if (lane == 0) { red[0][warp] = s1; red[1][warp] = s2; }
    __syncthreads();
    s1 = 0.f; s2 = 0.f;
#pragma unroll
    for (int w = 0; w < 8; w++) { s1 += red[0][w]; s2 += red[1][w]; }

    const float inv1 = 1.f / s1;
    const float inv2 = 1.f / s2;
    const float a = *alpha_p;
    const float bt = *beta_p;
#pragma unroll
    for (int j = 0; j < 4; j++) {
        const int k = tid + j * 256;
        const float p1 = er[j] * inv1;
        const float p2 = ed[j] * inv2;
        pr[k] = (1.f - a) * p1 + a * p2;
        pd[k] = (1.f - bt) * p2 + bt * p1;
    }
}

// ---------------------------------------------------------------------------
// Kernel 4: P @ V via tf32 mma, DOUBLE-BUFFERED.
// Block: 128 q rows x 32 d, 8 warps stacked in m (warp tile 16q x 32d).
// k-tiles of 32, smem ping-pong + register prefetch, one sync per tile.
// Probs streamed with __ldcs (read once, 268 MB).
// ---------------------------------------------------------------------------
__global__ __launch_bounds__(256) void pv_mma_kernel(const float* __restrict__ dout)
{
    __shared__ uint32_t Ps[2][128][36];
    __shared__ uint32_t Vs[2][32][36];
    const int z = blockIdx.y;
    const int st = z >> 5;
    const int bh = z & 31;
    const int bq = blockIdx.x * 128;

    const float* P = dout + OFF_SHARED + (size_t)st * BHSS + (size_t)bh * SDIM * SDIM;
    const float* V = g_qkv + ((size_t)(st * 3 + 2) * 32 + bh) * (SDIM * DDIM);

    const int tid = threadIdx.x;
    const int wid = tid >> 5;
    const int lane = tid & 31;
    const int gid = lane >> 2;
    const int tig = lane & 3;

    const int sr0 = tid >> 3;            // 0..31, +32*t
    const int sc0 = (tid & 7) * 4;

    float4 pp[4], pv;
    // prefetch tile 0
#pragma unroll
    for (int t = 0; t < 4; t++)
        pp[t] = __ldcs(reinterpret_cast<const float4*>(P + (size_t)(bq + sr0 + t * 32) * SDIM + sc0));
    pv = *reinterpret_cast<const float4*>(V + (size_t)sr0 * 32 + sc0);
    // store tile 0
#pragma unroll
    for (int t = 0; t < 4; t++) {
        const int r = sr0 + t * 32;
        Ps[0][r][sc0 + 0] = f2tf(pp[t].x); Ps[0][r][sc0 + 1] = f2tf(pp[t].y);
        Ps[0][r][sc0 + 2] = f2tf(pp[t].z); Ps[0][r][sc0 + 3] = f2tf(pp[t].w);
    }
    Vs[0][sr0][sc0 + 0] = f2tf(pv.x); Vs[0][sr0][sc0 + 1] = f2tf(pv.y);
    Vs[0][sr0][sc0 + 2] = f2tf(pv.z); Vs[0][sr0][sc0 + 3] = f2tf(pv.w);
    __syncthreads();

    float acc[4][4] = {};

    for (int kt = 0; kt < 32; kt++) {
        const int cur = kt & 1;
        // issue prefetch of next tile (long-latency loads first)
        if (kt < 31) {
            const int k0 = (kt + 1) * 32;
#pragma unroll
            for (int t = 0; t < 4; t++)
                pp[t] = __ldcs(reinterpret_cast<const float4*>(P + (size_t)(bq + sr0 + t * 32) * SDIM + k0 + sc0));
            pv = *reinterpret_cast<const float4*>(V + (size_t)(k0 + sr0) * 32 + sc0);
        }

        // compute on current buffer
#pragma unroll
        for (int kc = 0; kc < 4; kc++) {
            const int k8 = kc * 8;
            uint32_t a[4];
            const int r = wid * 16;
            a[0] = Ps[cur][r + gid][k8 + tig];
            a[1] = Ps[cur][r + gid + 8][k8 + tig];
            a[2] = Ps[cur][r + gid][k8 + tig + 4];
            a[3] = Ps[cur][r + gid + 8][k8 + tig + 4];
#pragma unroll
            for (int j = 0; j < 4; j++) {
                uint32_t bf[2];
                bf[0] = Vs[cur][k8 + tig][j * 8 + gid];
                bf[1] = Vs[cur][k8 + tig + 4][j * 8 + gid];
                mma_tf32(acc[j], a, bf);
            }
        }

        // write prefetched regs into the other buffer
        if (kt < 31) {
            const int nxt = cur ^ 1;
#pragma unroll
            for (int t = 0; t < 4; t++) {
                const int r = sr0 + t * 32;
                Ps[nxt][r][sc0 + 0] = f2tf(pp[t].x); Ps[nxt][r][sc0 + 1] = f2tf(pp[t].y);
                Ps[nxt][r][sc0 + 2] = f2tf(pp[t].z); Ps[nxt][r][sc0 + 3] = f2tf(pp[t].w);
            }
            Vs[nxt][sr0][sc0 + 0] = f2tf(pv.x); Vs[nxt][sr0][sc0 + 1] = f2tf(pv.y);
            Vs[nxt][sr0][sc0 + 2] = f2tf(pv.z); Vs[nxt][sr0][sc0 + 3] = f2tf(pv.w);
        }
        __syncthreads();
    }

    const int b = bh >> 3;
    const int h = bh & 7;
    const int q0 = bq + wid * 16 + gid;
#pragma unroll
    for (int j = 0; j < 4; j++) {
        const int d0 = j * 8 + tig * 2;
        float* o0 = &g_ocat[((size_t)(st * 4 + b) * SDIM + q0) * EDIM + h * 32 + d0];
        float* o1 = &g_ocat[((size_t)(st * 4 + b) * SDIM + q0 + 8) * EDIM + h * 32 + d0];
        *reinterpret_cast<float2*>(o0) = make_float2(acc[j][0], acc[j][1]);
        *reinterpret_cast<float2*>(o1) = make_float2(acc[j][2], acc[j][3]);
    }
}

// ---------------------------------------------------------------------------
// Kernel 5: batched output projection (fp32, accuracy headroom). grid.z = st.
// ---------------------------------------------------------------------------
struct OutArgs {
    const float* w[2];
    const float* b[2];
};

__global__ __launch_bounds__(256) void outproj_kernel(OutArgs args, float* __restrict__ dout)
{
    __shared__ float As[16][64];
    __shared__ float Bs[16][64];
    const int st = blockIdx.z;
    const float* W = args.w[st];
    const float* bias = args.b[st];
    float* out = dout + (size_t)st * (SDIM * BDIM * EDIM);

    const int bm = blockIdx.y * 64;
    const int bn = blockIdx.x * 64;
    const int tid = threadIdx.x;
    const int tx = tid & 15;
    const int ty = tid >> 4;
    const float* A = g_ocat + (size_t)st * (BDIM * SDIM * EDIM);

    float acc[4][4] = {};
    const int lrow = tid >> 2;
    const int lcol = (tid & 3) * 4;

    for (int k0 = 0; k0 < 256; k0 += 16) {
        float4 va = *reinterpret_cast<const float4*>(A + (size_t)(bm + lrow) * 256 + k0 + lcol);
        float4 vb = *reinterpret_cast<const float4*>(W + (size_t)(bn + lrow) * 256 + k0 + lcol);
        As[lcol + 0][lrow] = va.x; As[lcol + 1][lrow] = va.y;
        As[lcol + 2][lrow] = va.z; As[lcol + 3][lrow] = va.w;
        Bs[lcol + 0][lrow] = vb.x; Bs[lcol + 1][lrow] = vb.y;
        Bs[lcol + 2][lrow] = vb.z; Bs[lcol + 3][lrow] = vb.w;
        __syncthreads();
#pragma unroll
        for (int kk = 0; kk < 16; kk++) {
            float a[4], b[4];
#pragma unroll
            for (int i = 0; i < 4; i++) a[i] = As[kk][ty * 4 + i];
#pragma unroll
            for (int j = 0; j < 4; j++) b[j] = Bs[kk][tx * 4 + j];
#pragma unroll
            for (int i = 0; i < 4; i++)
#pragma unroll
                for (int j = 0; j < 4; j++) acc[i][j] += a[i] * b[j];
        }
        __syncthreads();
    }

#pragma unroll
    for (int i = 0; i < 4; i++) {
        const int m = bm + ty * 4 + i;     // m = b*1024 + s
        const int b = m >> 10;
        const int s = m & 1023;
#pragma unroll
        for (int j = 0; j < 4; j++) {
            const int n = bn + tx * 4 + j;
            out[(size_t)(s * 4 + b) * 256 + n] = acc[i][j] + bias[n];
        }
    }
}

// ---------------------------------------------------------------------------
extern "C" void kernel_launch(void* const* d_in, const int* in_sizes, int n_in,
                              void* d_out, int out_size)
{
    const unsigned char* mask = (const unsigned char*)d_in[6];
    const float* alpha = (const float*)d_in[15];
    const float* beta  = (const float*)d_in[16];
    float* out = (float*)d_out;

    // 1) all six QKV projections in one launch (tf32 mma)
    ProjArgs pa;
    for (int i = 0; i < 6; i++) pa.x[i] = (const float*)d_in[i];
    pa.w[0] = (const float*)d_in[7];  pa.b[0] = (const float*)d_in[8];
    pa.w[1] = (const float*)d_in[11]; pa.b[1] = (const float*)d_in[12];
    proj_tf32_kernel<<<dim3(2, 32, 6), 256>>>(pa);

    // 2) attention scores via tf32 mma (raw) into shared_* slots of d_out
    scores_mma_kernel<<<dim3(8, 8, 64), 256>>>(out);

    // 3) softmax both streams + blend, in place
    softmax_blend_kernel<<<BDIM * HDIM * SDIM, 256>>>(out, mask, alpha, beta);

    // 4) P @ V via tf32 mma, double-buffered
    pv_mma_kernel<<<dim3(8, 64), 256>>>(out);

    // 5) both output projections in one launch (fp32)
    OutArgs oa;
    oa.w[0] = (const float*)d_in[9];  oa.b[0] = (const float*)d_in[10];
    oa.w[1] = (const float*)d_in[13]; oa.b[1] = (const float*)d_in[14];
    outproj_kernel<<<dim3(4, 64, 2), 256>>>(oa, out);
}

// round 7
// speedup vs baseline: 1.7031x; 1.0716x over previous
#include <cuda_runtime.h>
#include <cuda_bf16.h>
#include <math_constants.h>
#include <cstdint>

// Problem constants
#define SDIM 1024
#define BDIM 4
#define EDIM 256
#define HDIM 8
#define DDIM 32

// d_out layout: out_rgb [S,B,E], out_dpt [S,B,E], shared_rgb [B,H,S,S], shared_dpt [B,H,S,S]
#define OFF_OUT_RGB  0
#define OFF_OUT_DPT  (SDIM*BDIM*EDIM)              // 1048576
#define OFF_SHARED   (2*SDIM*BDIM*EDIM)            // 2097152
#define BHSS         ((size_t)BDIM*HDIM*SDIM*SDIM) // 33554432

#define SCALE 0.17677669529663687f   // 1/sqrt(32)

// Scratch
__device__ float g_qkv[6 * BDIM * HDIM * SDIM * DDIM];   // 25 MB
__device__ float g_ocat[2 * BDIM * SDIM * EDIM];         // 8 MB
__device__ float g_sums[2 * 32 * SDIM];                  // exp-sums per (st,bh,q)

// ---------------------------------------------------------------------------
// tf32 helpers (mma.sync m16n8k8, fp32 accum)
// ---------------------------------------------------------------------------
__device__ __forceinline__ uint32_t f2tf(float f) {
    uint32_t u;
    asm("cvt.rna.tf32.f32 %0, %1;" : "=r"(u) : "f"(f));
    return u;
}

__device__ __forceinline__ void mma_tf32(float* d, const uint32_t* a, const uint32_t* b) {
    asm volatile(
        "mma.sync.aligned.m16n8k8.row.col.f32.tf32.tf32.f32 "
        "{%0,%1,%2,%3}, {%4,%5,%6,%7}, {%8,%9}, {%0,%1,%2,%3};"
        : "+f"(d[0]), "+f"(d[1]), "+f"(d[2]), "+f"(d[3])
        : "r"(a[0]), "r"(a[1]), "r"(a[2]), "r"(a[3]),
          "r"(b[0]), "r"(b[1]));
}

// ---------------------------------------------------------------------------
// Kernel 0: zero the sums accumulator (graph-replayed every launch)
// ---------------------------------------------------------------------------
__global__ void zero_sums_kernel() {
    g_sums[blockIdx.x * 256 + threadIdx.x] = 0.f;
}

// ---------------------------------------------------------------------------
// Kernel 1: batched QKV projection via tf32 mma. grid.z = proj id 0..5.
// ---------------------------------------------------------------------------
struct ProjArgs {
    const float* x[6];
    const float* w[2];
    const float* b[2];
};

__global__ __launch_bounds__(256) void proj_tf32_kernel(ProjArgs args)
{
    __shared__ uint32_t As[128][36];
    __shared__ uint32_t Bs[128][36];
    const int proj = blockIdx.z;
    const int st = proj / 3;
    const int wsel = proj - st * 3;
    const float* x = args.x[proj];
    const float* W = args.w[st] + (size_t)wsel * 256 * 256;
    const float* bias = args.b[st] + wsel * 256;

    const int bm = blockIdx.y * 128;
    const int bn = blockIdx.x * 128;
    const int tid = threadIdx.x;
    const int wid = tid >> 5;
    const int lane = tid & 31;
    const int gid = lane >> 2;
    const int tig = lane & 3;
    const int wm = (wid & 3) * 32;
    const int wn = (wid >> 2) * 64;

    const int sr0 = tid >> 3;            // 0..31, +32*t
    const int sc0 = (tid & 7) * 4;       // 0,4,..28

    float4 pa[4], pb[4];
#pragma unroll
    for (int t = 0; t < 4; t++) {
        pa[t] = *reinterpret_cast<const float4*>(x + (size_t)(bm + sr0 + t * 32) * 256 + sc0);
        pb[t] = *reinterpret_cast<const float4*>(W + (size_t)(bn + sr0 + t * 32) * 256 + sc0);
    }

    float acc[2][8][4] = {};

    for (int kt = 0; kt < 8; kt++) {
#pragma unroll
        for (int t = 0; t < 4; t++) {
            const int r = sr0 + t * 32;
            As[r][sc0 + 0] = f2tf(pa[t].x); As[r][sc0 + 1] = f2tf(pa[t].y);
            As[r][sc0 + 2] = f2tf(pa[t].z); As[r][sc0 + 3] = f2tf(pa[t].w);
            Bs[r][sc0 + 0] = f2tf(pb[t].x); Bs[r][sc0 + 1] = f2tf(pb[t].y);
            Bs[r][sc0 + 2] = f2tf(pb[t].z); Bs[r][sc0 + 3] = f2tf(pb[t].w);
        }
        __syncthreads();

        if (kt < 7) {
            const int k0 = (kt + 1) * 32;
#pragma unroll
            for (int t = 0; t < 4; t++) {
                pa[t] = *reinterpret_cast<const float4*>(x + (size_t)(bm + sr0 + t * 32) * 256 + k0 + sc0);
                pb[t] = *reinterpret_cast<const float4*>(W + (size_t)(bn + sr0 + t * 32) * 256 + k0 + sc0);
            }
        }

#pragma unroll
        for (int kc = 0; kc < 4; kc++) {
            const int k8 = kc * 8;
            uint32_t a[2][4], b[8][2];
#pragma unroll
            for (int i = 0; i < 2; i++) {
                const int r = wm + i * 16;
                a[i][0] = As[r + gid][k8 + tig];
                a[i][1] = As[r + gid + 8][k8 + tig];
                a[i][2] = As[r + gid][k8 + tig + 4];
                a[i][3] = As[r + gid + 8][k8 + tig + 4];
            }
#pragma unroll
            for (int j = 0; j < 8; j++) {
                const int c = wn + j * 8;
                b[j][0] = Bs[c + gid][k8 + tig];
                b[j][1] = Bs[c + gid][k8 + tig + 4];
            }
#pragma unroll
            for (int i = 0; i < 2; i++)
#pragma unroll
                for (int j = 0; j < 8; j++)
                    mma_tf32(acc[i][j], a[i], b[j]);
        }
        __syncthreads();
    }

#pragma unroll
    for (int i = 0; i < 2; i++) {
        const int m0 = bm + wm + i * 16 + gid;
        const int s0 = m0 >> 2, b0 = m0 & 3;
        const int m1 = m0 + 8;
        const int s1 = m1 >> 2, b1 = m1 & 3;
#pragma unroll
        for (int j = 0; j < 8; j++) {
            const int c0 = bn + wn + j * 8 + tig * 2;
            const int h = c0 >> 5;
            const int d = c0 & 31;
            const float bv0 = bias[c0], bv1 = bias[c0 + 1];
            float* p0 = &g_qkv[(((size_t)(proj * 4 + b0) * 8 + h) * 1024 + s0) * 32 + d];
            float* p1 = &g_qkv[(((size_t)(proj * 4 + b1) * 8 + h) * 1024 + s1) * 32 + d];
            *reinterpret_cast<float2*>(p0) = make_float2(acc[i][j][0] + bv0, acc[i][j][1] + bv1);
            *reinterpret_cast<float2*>(p1) = make_float2(acc[i][j][2] + bv0, acc[i][j][3] + bv1);
        }
    }
}

// ---------------------------------------------------------------------------
// Kernel 2: scores via tf32 mma + per-row exp-sum stats (atomicAdd to g_sums).
// Raw scaled scores written (streaming) to shared_* slots of d_out.
// No max-subtraction: scores are O(1) for this problem; exp(s) is safe and
// softmax is shift-invariant.
// ---------------------------------------------------------------------------
__global__ __launch_bounds__(256) void scores_mma_kernel(
    float* __restrict__ dout, const unsigned char* __restrict__ mask)
{
    __shared__ uint32_t Qs[128][36];
    __shared__ uint32_t Ks[128][36];
    const int z = blockIdx.z;
    const int st = z >> 5;
    const int bh = z & 31;
    const int bq = blockIdx.y * 128;
    const int bk = blockIdx.x * 128;

    const float* Q = g_qkv + ((size_t)(st * 3 + 0) * 32 + bh) * (SDIM * DDIM);
    const float* K = g_qkv + ((size_t)(st * 3 + 1) * 32 + bh) * (SDIM * DDIM);

    const int tid = threadIdx.x;
    for (int i = tid * 4; i < 128 * 32; i += 1024) {
        const int r = i >> 5, c = i & 31;
        float4 q4 = *reinterpret_cast<const float4*>(Q + (size_t)(bq + r) * 32 + c);
        float4 k4 = *reinterpret_cast<const float4*>(K + (size_t)(bk + r) * 32 + c);
        Qs[r][c + 0] = f2tf(q4.x); Qs[r][c + 1] = f2tf(q4.y);
        Qs[r][c + 2] = f2tf(q4.z); Qs[r][c + 3] = f2tf(q4.w);
        Ks[r][c + 0] = f2tf(k4.x); Ks[r][c + 1] = f2tf(k4.y);
        Ks[r][c + 2] = f2tf(k4.z); Ks[r][c + 3] = f2tf(k4.w);
    }
    __syncthreads();

    const int wid = tid >> 5;
    const int lane = tid & 31;
    const int gid = lane >> 2;
    const int tig = lane & 3;
    const int wm = (wid & 3) * 32;
    const int wn = (wid >> 2) * 64;

    float acc[2][8][4] = {};
#pragma unroll
    for (int kc = 0; kc < 4; kc++) {
        const int k0 = kc * 8;
        uint32_t a[2][4], b[8][2];
#pragma unroll
        for (int i = 0; i < 2; i++) {
            const int r = wm + i * 16;
            a[i][0] = Qs[r + gid][k0 + tig];
            a[i][1] = Qs[r + gid + 8][k0 + tig];
            a[i][2] = Qs[r + gid][k0 + tig + 4];
            a[i][3] = Qs[r + gid + 8][k0 + tig + 4];
        }
#pragma unroll
        for (int j = 0; j < 8; j++) {
            const int c = wn + j * 8;
            b[j][0] = Ks[c + gid][k0 + tig];
            b[j][1] = Ks[c + gid][k0 + tig + 4];
        }
#pragma unroll
        for (int i = 0; i < 2; i++)
#pragma unroll
            for (int j = 0; j < 8; j++)
                mma_tf32(acc[i][j], a[i], b[j]);
    }

    // scale in place
#pragma unroll
    for (int i = 0; i < 2; i++)
#pragma unroll
        for (int j = 0; j < 8; j++)
#pragma unroll
            for (int v = 0; v < 4; v++) acc[i][j][v] *= SCALE;

    // per-row exp sums (masked cols contribute 0)
    const unsigned char* mrow = mask + (size_t)(bh >> 3) * SDIM;
    float* sums = g_sums + (size_t)z * SDIM;
#pragma unroll
    for (int i = 0; i < 2; i++) {
        float slo = 0.f, shi = 0.f;
#pragma unroll
        for (int j = 0; j < 8; j++) {
            const int c0 = bk + wn + j * 8 + tig * 2;
            const float m0 = mrow[c0] ? 0.f : 1.f;
            const float m1 = mrow[c0 + 1] ? 0.f : 1.f;
            slo += m0 * __expf(acc[i][j][0]) + m1 * __expf(acc[i][j][1]);
            shi += m0 * __expf(acc[i][j][2]) + m1 * __expf(acc[i][j][3]);
        }
        slo += __shfl_xor_sync(0xffffffffu, slo, 1);
        slo += __shfl_xor_sync(0xffffffffu, slo, 2);
        shi += __shfl_xor_sync(0xffffffffu, shi, 1);
        shi += __shfl_xor_sync(0xffffffffu, shi, 2);
        if (tig == 0) {
            atomicAdd(&sums[bq + wm + i * 16 + gid], slo);
            atomicAdd(&sums[bq + wm + i * 16 + gid + 8], shi);
        }
    }

    // write raw scaled scores (streaming — consumed once by pv_fused)
    float* out = dout + OFF_SHARED + (size_t)st * BHSS + (size_t)bh * SDIM * SDIM;
#pragma unroll
    for (int i = 0; i < 2; i++) {
        const int q0 = bq + wm + i * 16 + gid;
#pragma unroll
        for (int j = 0; j < 8; j++) {
            const int c0 = bk + wn + j * 8 + tig * 2;
            __stcs(reinterpret_cast<float2*>(out + (size_t)q0 * SDIM + c0),
                   make_float2(acc[i][j][0], acc[i][j][1]));
            __stcs(reinterpret_cast<float2*>(out + (size_t)(q0 + 8) * SDIM + c0),
                   make_float2(acc[i][j][2], acc[i][j][3]));
        }
    }
}

// ---------------------------------------------------------------------------
// Kernel 3 (FUSED): exp + normalize + blend + prob write + P@V (tf32 mma).
// Block: 128 q rows x 32 d, BOTH streams, one (b,h). Double-buffered k-tiles
// of 32. Raw scores read once (ldcs), blended probs written once (stcs,
// in-place over the raw scores), tf32 probs fed to mma from smem.
// Dynamic smem 92160 B; 2 CTAs/SM.
// ---------------------------------------------------------------------------
#define PS_OFF(buf,st) (((buf)*2+(st))*128*36)
#define VS_OFF(buf,st) (4*128*36 + ((buf)*2+(st))*32*36)
#define PV_SMEM ((4*128*36 + 4*32*36) * 4)   // 92160 bytes

struct PVRegs { float4 s1[4], s2[4], v1, v2; uchar4 m4; };

__device__ __forceinline__ void pv_load(PVRegs& R,
    const float* __restrict__ S1, const float* __restrict__ S2,
    const float* __restrict__ V1, const float* __restrict__ V2,
    const unsigned char* __restrict__ mrow, int k0, int sr0, int sc0)
{
#pragma unroll
    for (int t = 0; t < 4; t++) {
        R.s1[t] = __ldcs(reinterpret_cast<const float4*>(S1 + (size_t)(sr0 + 32 * t) * SDIM + k0 + sc0));
        R.s2[t] = __ldcs(reinterpret_cast<const float4*>(S2 + (size_t)(sr0 + 32 * t) * SDIM + k0 + sc0));
    }
    R.v1 = *reinterpret_cast<const float4*>(V1 + (size_t)(k0 + sr0) * DDIM + sc0);
    R.v2 = *reinterpret_cast<const float4*>(V2 + (size_t)(k0 + sr0) * DDIM + sc0);
    R.m4 = *reinterpret_cast<const uchar4*>(mrow + k0 + sc0);
}

__device__ __forceinline__ void pv_store(const PVRegs& R, uint32_t* sm, int buf,
    float* __restrict__ S1, float* __restrict__ S2,
    int k0, int sr0, int sc0,
    const float* inv1, const float* inv2, float a, float bt)
{
    const float mx = R.m4.x ? 0.f : 1.f;
    const float my = R.m4.y ? 0.f : 1.f;
    const float mz = R.m4.z ? 0.f : 1.f;
    const float mw = R.m4.w ? 0.f : 1.f;
#pragma unroll
    for (int t = 0; t < 4; t++) {
        const int r = sr0 + 32 * t;
        const float q1 = inv1[t], q2 = inv2[t];
        float n1x = mx * __expf(R.s1[t].x) * q1, n2x = mx * __expf(R.s2[t].x) * q2;
        float n1y = my * __expf(R.s1[t].y) * q1, n2y = my * __expf(R.s2[t].y) * q2;
        float n1z = mz * __expf(R.s1[t].z) * q1, n2z = mz * __expf(R.s2[t].z) * q2;
        float n1w = mw * __expf(R.s1[t].w) * q1, n2w = mw * __expf(R.s2[t].w) * q2;
        float4 p1 = make_float4((1.f - a) * n1x + a * n2x, (1.f - a) * n1y + a * n2y,
                                (1.f - a) * n1z + a * n2z, (1.f - a) * n1w + a * n2w);
        float4 p2 = make_float4((1.f - bt) * n2x + bt * n1x, (1.f - bt) * n2y + bt * n1y,
                                (1.f - bt) * n2z + bt * n1z, (1.f - bt) * n2w + bt * n1w);
        __stcs(reinterpret_cast<float4*>(S1 + (size_t)r * SDIM + k0 + sc0), p1);
        __stcs(reinterpret_cast<float4*>(S2 + (size_t)r * SDIM + k0 + sc0), p2);
        uint32_t* P1 = sm + PS_OFF(buf, 0) + r * 36 + sc0;
        P1[0] = f2tf(p1.x); P1[1] = f2tf(p1.y); P1[2] = f2tf(p1.z); P1[3] = f2tf(p1.w);
        uint32_t* P2 = sm + PS_OFF(buf, 1) + r * 36 + sc0;
        P2[0] = f2tf(p2.x); P2[1] = f2tf(p2.y); P2[2] = f2tf(p2.z); P2[3] = f2tf(p2.w);
    }
    uint32_t* Va = sm + VS_OFF(buf, 0) + sr0 * 36 + sc0;
    Va[0] = f2tf(R.v1.x); Va[1] = f2tf(R.v1.y); Va[2] = f2tf(R.v1.z); Va[3] = f2tf(R.v1.w);
    uint32_t* Vb = sm + VS_OFF(buf, 1) + sr0 * 36 + sc0;
    Vb[0] = f2tf(R.v2.x); Vb[1] = f2tf(R.v2.y); Vb[2] = f2tf(R.v2.z); Vb[3] = f2tf(R.v2.w);
}

__global__ __launch_bounds__(256, 2) void pv_fused_kernel(
    float* __restrict__ dout, const unsigned char* __restrict__ mask,
    const float* __restrict__ alpha_p, const float* __restrict__ beta_p)
{
    extern __shared__ uint32_t sm[];
    const int bh = blockIdx.y;
    const int b = bh >> 3, h = bh & 7;
    const int bq = blockIdx.x * 128;

    float* S1 = dout + OFF_SHARED + ((size_t)bh * SDIM + bq) * SDIM;   // raw scores -> probs (in place)
    float* S2 = S1 + BHSS;
    const float* V1 = g_qkv + ((size_t)(0 * 3 + 2) * 32 + bh) * (SDIM * DDIM);
    const float* V2 = g_qkv + ((size_t)(1 * 3 + 2) * 32 + bh) * (SDIM * DDIM);
    const unsigned char* mrow = mask + (size_t)b * SDIM;

    const int tid = threadIdx.x;
    const int wid = tid >> 5;
    const int lane = tid & 31;
    const int gid = lane >> 2;
    const int tig = lane & 3;
    const int sr0 = tid >> 3;          // 0..31
    const int sc0 = (tid & 7) * 4;

    const float a = *alpha_p, bt = *beta_p;
    float inv1[4], inv2[4];
#pragma unroll
    for (int t = 0; t < 4; t++) {
        const int q = bq + sr0 + 32 * t;
        inv1[t] = 1.f / g_sums[(size_t)bh * SDIM + q];
        inv2[t] = 1.f / g_sums[(size_t)32 * SDIM + (size_t)bh * SDIM + q];
    }

    PVRegs R;
    pv_load(R, S1, S2, V1, V2, mrow, 0, sr0, sc0);
    pv_store(R, sm, 0, S1, S2, 0, sr0, sc0, inv1, inv2, a, bt);
    __syncthreads();

    float acc[2][4][4] = {};

    for (int kt = 0; kt < 32; kt++) {
        const int cur = kt & 1;
        if (kt < 31)
            pv_load(R, S1, S2, V1, V2, mrow, (kt + 1) * 32, sr0, sc0);

        // mma on current buffer, both streams
#pragma unroll
        for (int st = 0; st < 2; st++) {
            const uint32_t* P = sm + PS_OFF(cur, st);
            const uint32_t* Vt = sm + VS_OFF(cur, st);
            const int r = wid * 16;
#pragma unroll
            for (int kc = 0; kc < 4; kc++) {
                const int k8 = kc * 8;
                uint32_t av[4];
                av[0] = P[(r + gid) * 36 + k8 + tig];
                av[1] = P[(r + gid + 8) * 36 + k8 + tig];
                av[2] = P[(r + gid) * 36 + k8 + tig + 4];
                av[3] = P[(r + gid + 8) * 36 + k8 + tig + 4];
#pragma unroll
                for (int j = 0; j < 4; j++) {
                    uint32_t bf[2];
                    bf[0] = Vt[(k8 + tig) * 36 + j * 8 + gid];
                    bf[1] = Vt[(k8 + tig + 4) * 36 + j * 8 + gid];
                    mma_tf32(acc[st][j], av, bf);
                }
            }
        }

        if (kt < 31)
            pv_store(R, sm, cur ^ 1, S1, S2, (kt + 1) * 32, sr0, sc0, inv1, inv2, a, bt);
        __syncthreads();
    }

    const int q0 = bq + wid * 16 + gid;
#pragma unroll
    for (int st = 0; st < 2; st++) {
#pragma unroll
        for (int j = 0; j < 4; j++) {
            const int d0 = j * 8 + tig * 2;
            float* o0 = &g_ocat[((size_t)(st * 4 + b) * SDIM + q0) * EDIM + h * 32 + d0];
            float* o1 = &g_ocat[((size_t)(st * 4 + b) * SDIM + q0 + 8) * EDIM + h * 32 + d0];
            *reinterpret_cast<float2*>(o0) = make_float2(acc[st][j][0], acc[st][j][1]);
            *reinterpret_cast<float2*>(o1) = make_float2(acc[st][j][2], acc[st][j][3]);
        }
    }
}

// ---------------------------------------------------------------------------
// Kernel 4: batched output projection (fp32, accuracy headroom). grid.z = st.
// ---------------------------------------------------------------------------
struct OutArgs {
    const float* w[2];
    const float* b[2];
};

__global__ __launch_bounds__(256) void outproj_kernel(OutArgs args, float* __restrict__ dout)
{
    __shared__ float As[16][64];
    __shared__ float Bs[16][64];
    const int st = blockIdx.z;
    const float* W = args.w[st];
    const float* bias = args.b[st];
    float* out = dout + (size_t)st * (SDIM * BDIM * EDIM);

    const int bm = blockIdx.y * 64;
    const int bn = blockIdx.x * 64;
    const int tid = threadIdx.x;
    const int tx = tid & 15;
    const int ty = tid >> 4;
    const float* A = g_ocat + (size_t)st * (BDIM * SDIM * EDIM);

    float acc[4][4] = {};
    const int lrow = tid >> 2;
    const int lcol = (tid & 3) * 4;

    for (int k0 = 0; k0 < 256; k0 += 16) {
        float4 va = *reinterpret_cast<const float4*>(A + (size_t)(bm + lrow) * 256 + k0 + lcol);
        float4 vb = *reinterpret_cast<const float4*>(W + (size_t)(bn + lrow) * 256 + k0 + lcol);
        As[lcol + 0][lrow] = va.x; As[lcol + 1][lrow] = va.y;
        As[lcol + 2][lrow] = va.z; As[lcol + 3][lrow] = va.w;
        Bs[lcol + 0][lrow] = vb.x; Bs[lcol + 1][lrow] = vb.y;
        Bs[lcol + 2][lrow] = vb.z; Bs[lcol + 3][lrow] = vb.w;
        __syncthreads();
#pragma unroll
        for (int kk = 0; kk < 16; kk++) {
            float a[4], b[4];
#pragma unroll
            for (int i = 0; i < 4; i++) a[i] = As[kk][ty * 4 + i];
#pragma unroll
            for (int j = 0; j < 4; j++) b[j] = Bs[kk][tx * 4 + j];
#pragma unroll
            for (int i = 0; i < 4; i++)
#pragma unroll
                for (int j = 0; j < 4; j++) acc[i][j] += a[i] * b[j];
        }
        __syncthreads();
    }

#pragma unroll
    for (int i = 0; i < 4; i++) {
        const int m = bm + ty * 4 + i;     // m = b*1024 + s
        const int b = m >> 10;
        const int s = m & 1023;
#pragma unroll
        for (int j = 0; j < 4; j++) {
            const int n = bn + tx * 4 + j;
            out[(size_t)(s * 4 + b) * 256 + n] = acc[i][j] + bias[n];
        }
    }
}

// ---------------------------------------------------------------------------
extern "C" void kernel_launch(void* const* d_in, const int* in_sizes, int n_in,
                              void* d_out, int out_size)
{
    const unsigned char* mask = (const unsigned char*)d_in[6];
    const float* alpha = (const float*)d_in[15];
    const float* beta  = (const float*)d_in[16];
    float* out = (float*)d_out;

    cudaFuncSetAttribute(pv_fused_kernel,
                         cudaFuncAttributeMaxDynamicSharedMemorySize, PV_SMEM);

    // 0) zero exp-sum accumulators
    zero_sums_kernel<<<256, 256>>>();

    // 1) all six QKV projections in one launch (tf32 mma)
    ProjArgs pa;
    for (int i = 0; i < 6; i++) pa.x[i] = (const float*)d_in[i];
    pa.w[0] = (const float*)d_in[7];  pa.b[0] = (const float*)d_in[8];
    pa.w[1] = (const float*)d_in[11]; pa.b[1] = (const float*)d_in[12];
    proj_tf32_kernel<<<dim3(2, 32, 6), 256>>>(pa);

    // 2) scores + exp-sum stats (raw scores into shared_* slots of d_out)
    scores_mma_kernel<<<dim3(8, 8, 64), 256>>>(out, mask);

    // 3) fused normalize + blend + prob write + P@V
    pv_fused_kernel<<<dim3(8, 32), 256, PV_SMEM>>>(out, mask, alpha, beta);

    // 4) both output projections in one launch (fp32)
    OutArgs oa;
    oa.w[0] = (const float*)d_in[9];  oa.b[0] = (const float*)d_in[10];
    oa.w[1] = (const float*)d_in[13]; oa.b[1] = (const float*)d_in[14];
    outproj_kernel<<<dim3(4, 64, 2), 256>>>(oa, out);
}

// round 8
// speedup vs baseline: 1.7937x; 1.0532x over previous
#include <cuda_runtime.h>
#include <cuda_bf16.h>
#include <math_constants.h>
#include <cstdint>

// Problem constants
#define SDIM 1024
#define BDIM 4
#define EDIM 256
#define HDIM 8
#define DDIM 32

// d_out layout: out_rgb [S,B,E], out_dpt [S,B,E], shared_rgb [B,H,S,S], shared_dpt [B,H,S,S]
#define OFF_OUT_RGB  0
#define OFF_OUT_DPT  (SDIM*BDIM*EDIM)              // 1048576
#define OFF_SHARED   (2*SDIM*BDIM*EDIM)            // 2097152
#define BHSS         ((size_t)BDIM*HDIM*SDIM*SDIM) // 33554432

#define SCALE 0.17677669529663687f   // 1/sqrt(32)

// Scratch
__device__ float g_qkv[6 * BDIM * HDIM * SDIM * DDIM];   // 25 MB
__device__ float g_ocat[2 * BDIM * SDIM * EDIM];         // 8 MB
__device__ float g_sums[2 * 32 * SDIM];                  // exp-sums per (st,bh,q)

// ---------------------------------------------------------------------------
// tf32 helpers (mma.sync m16n8k8, fp32 accum)
// ---------------------------------------------------------------------------
__device__ __forceinline__ uint32_t f2tf(float f) {
    uint32_t u;
    asm("cvt.rna.tf32.f32 %0, %1;" : "=r"(u) : "f"(f));
    return u;
}

__device__ __forceinline__ void mma_tf32(float* d, const uint32_t* a, const uint32_t* b) {
    asm volatile(
        "mma.sync.aligned.m16n8k8.row.col.f32.tf32.tf32.f32 "
        "{%0,%1,%2,%3}, {%4,%5,%6,%7}, {%8,%9}, {%0,%1,%2,%3};"
        : "+f"(d[0]), "+f"(d[1]), "+f"(d[2]), "+f"(d[3])
        : "r"(a[0]), "r"(a[1]), "r"(a[2]), "r"(a[3]),
          "r"(b[0]), "r"(b[1]));
}

// ---------------------------------------------------------------------------
// Kernel 0: zero the sums accumulator (graph-replayed every launch)
// ---------------------------------------------------------------------------
__global__ void zero_sums_kernel() {
    g_sums[blockIdx.x * 256 + threadIdx.x] = 0.f;
}

// ---------------------------------------------------------------------------
// Kernel 1: batched QKV projection via tf32 mma. grid.z = proj id 0..5.
// ---------------------------------------------------------------------------
struct ProjArgs {
    const float* x[6];
    const float* w[2];
    const float* b[2];
};

__global__ __launch_bounds__(256) void proj_tf32_kernel(ProjArgs args)
{
    __shared__ uint32_t As[128][36];
    __shared__ uint32_t Bs[128][36];
    const int proj = blockIdx.z;
    const int st = proj / 3;
    const int wsel = proj - st * 3;
    const float* x = args.x[proj];
    const float* W = args.w[st] + (size_t)wsel * 256 * 256;
    const float* bias = args.b[st] + wsel * 256;

    const int bm = blockIdx.y * 128;
    const int bn = blockIdx.x * 128;
    const int tid = threadIdx.x;
    const int wid = tid >> 5;
    const int lane = tid & 31;
    const int gid = lane >> 2;
    const int tig = lane & 3;
    const int wm = (wid & 3) * 32;
    const int wn = (wid >> 2) * 64;

    const int sr0 = tid >> 3;            // 0..31, +32*t
    const int sc0 = (tid & 7) * 4;       // 0,4,..28

    float4 pa[4], pb[4];
#pragma unroll
    for (int t = 0; t < 4; t++) {
        pa[t] = *reinterpret_cast<const float4*>(x + (size_t)(bm + sr0 + t * 32) * 256 + sc0);
        pb[t] = *reinterpret_cast<const float4*>(W + (size_t)(bn + sr0 + t * 32) * 256 + sc0);
    }

    float acc[2][8][4] = {};

    for (int kt = 0; kt < 8; kt++) {
#pragma unroll
        for (int t = 0; t < 4; t++) {
            const int r = sr0 + t * 32;
            As[r][sc0 + 0] = f2tf(pa[t].x); As[r][sc0 + 1] = f2tf(pa[t].y);
            As[r][sc0 + 2] = f2tf(pa[t].z); As[r][sc0 + 3] = f2tf(pa[t].w);
            Bs[r][sc0 + 0] = f2tf(pb[t].x); Bs[r][sc0 + 1] = f2tf(pb[t].y);
            Bs[r][sc0 + 2] = f2tf(pb[t].z); Bs[r][sc0 + 3] = f2tf(pb[t].w);
        }
        __syncthreads();

        if (kt < 7) {
            const int k0 = (kt + 1) * 32;
#pragma unroll
            for (int t = 0; t < 4; t++) {
                pa[t] = *reinterpret_cast<const float4*>(x + (size_t)(bm + sr0 + t * 32) * 256 + k0 + sc0);
                pb[t] = *reinterpret_cast<const float4*>(W + (size_t)(bn + sr0 + t * 32) * 256 + k0 + sc0);
            }
        }

#pragma unroll
        for (int kc = 0; kc < 4; kc++) {
            const int k8 = kc * 8;
            uint32_t a[2][4], b[8][2];
#pragma unroll
            for (int i = 0; i < 2; i++) {
                const int r = wm + i * 16;
                a[i][0] = As[r + gid][k8 + tig];
                a[i][1] = As[r + gid + 8][k8 + tig];
                a[i][2] = As[r + gid][k8 + tig + 4];
                a[i][3] = As[r + gid + 8][k8 + tig + 4];
            }
#pragma unroll
            for (int j = 0; j < 8; j++) {
                const int c = wn + j * 8;
                b[j][0] = Bs[c + gid][k8 + tig];
                b[j][1] = Bs[c + gid][k8 + tig + 4];
            }
#pragma unroll
            for (int i = 0; i < 2; i++)
#pragma unroll
                for (int j = 0; j < 8; j++)
                    mma_tf32(acc[i][j], a[i], b[j]);
        }
        __syncthreads();
    }

#pragma unroll
    for (int i = 0; i < 2; i++) {
        const int m0 = bm + wm + i * 16 + gid;
        const int s0 = m0 >> 2, b0 = m0 & 3;
        const int m1 = m0 + 8;
        const int s1 = m1 >> 2, b1 = m1 & 3;
#pragma unroll
        for (int j = 0; j < 8; j++) {
            const int c0 = bn + wn + j * 8 + tig * 2;
            const int h = c0 >> 5;
            const int d = c0 & 31;
            const float bv0 = bias[c0], bv1 = bias[c0 + 1];
            float* p0 = &g_qkv[(((size_t)(proj * 4 + b0) * 8 + h) * 1024 + s0) * 32 + d];
            float* p1 = &g_qkv[(((size_t)(proj * 4 + b1) * 8 + h) * 1024 + s1) * 32 + d];
            *reinterpret_cast<float2*>(p0) = make_float2(acc[i][j][0] + bv0, acc[i][j][1] + bv1);
            *reinterpret_cast<float2*>(p1) = make_float2(acc[i][j][2] + bv0, acc[i][j][3] + bv1);
        }
    }
}

// ---------------------------------------------------------------------------
// Kernel 2: exp-sum stats only (no score writes). QK^T via tf32 mma,
// per-row sum of exp(scaled score) with mask, atomicAdd into g_sums.
// Accumulation order matches attn_fused_kernel exactly -> identical values.
// ---------------------------------------------------------------------------
__global__ __launch_bounds__(256) void sums_kernel(const unsigned char* __restrict__ mask)
{
    __shared__ uint32_t Qs[128][36];
    __shared__ uint32_t Ks[128][36];
    const int z = blockIdx.z;
    const int st = z >> 5;
    const int bh = z & 31;
    const int bq = blockIdx.y * 128;
    const int bk = blockIdx.x * 128;

    const float* Q = g_qkv + ((size_t)(st * 3 + 0) * 32 + bh) * (SDIM * DDIM);
    const float* K = g_qkv + ((size_t)(st * 3 + 1) * 32 + bh) * (SDIM * DDIM);

    const int tid = threadIdx.x;
    for (int i = tid * 4; i < 128 * 32; i += 1024) {
        const int r = i >> 5, c = i & 31;
        float4 q4 = *reinterpret_cast<const float4*>(Q + (size_t)(bq + r) * 32 + c);
        float4 k4 = *reinterpret_cast<const float4*>(K + (size_t)(bk + r) * 32 + c);
        Qs[r][c + 0] = f2tf(q4.x); Qs[r][c + 1] = f2tf(q4.y);
        Qs[r][c + 2] = f2tf(q4.z); Qs[r][c + 3] = f2tf(q4.w);
        Ks[r][c + 0] = f2tf(k4.x); Ks[r][c + 1] = f2tf(k4.y);
        Ks[r][c + 2] = f2tf(k4.z); Ks[r][c + 3] = f2tf(k4.w);
    }
    __syncthreads();

    const int wid = tid >> 5;
    const int lane = tid & 31;
    const int gid = lane >> 2;
    const int tig = lane & 3;
    const int wm = (wid & 3) * 32;
    const int wn = (wid >> 2) * 64;

    float acc[2][8][4] = {};
#pragma unroll
    for (int kc = 0; kc < 4; kc++) {
        const int k0 = kc * 8;
        uint32_t a[2][4], b[8][2];
#pragma unroll
        for (int i = 0; i < 2; i++) {
            const int r = wm + i * 16;
            a[i][0] = Qs[r + gid][k0 + tig];
            a[i][1] = Qs[r + gid + 8][k0 + tig];
            a[i][2] = Qs[r + gid][k0 + tig + 4];
            a[i][3] = Qs[r + gid + 8][k0 + tig + 4];
        }
#pragma unroll
        for (int j = 0; j < 8; j++) {
            const int c = wn + j * 8;
            b[j][0] = Ks[c + gid][k0 + tig];
            b[j][1] = Ks[c + gid][k0 + tig + 4];
        }
#pragma unroll
        for (int i = 0; i < 2; i++)
#pragma unroll
            for (int j = 0; j < 8; j++)
                mma_tf32(acc[i][j], a[i], b[j]);
    }

    const unsigned char* mrow = mask + (size_t)(bh >> 3) * SDIM;
    float* sums = g_sums + (size_t)z * SDIM;
#pragma unroll
    for (int i = 0; i < 2; i++) {
        float slo = 0.f, shi = 0.f;
#pragma unroll
        for (int j = 0; j < 8; j++) {
            const int c0 = bk + wn + j * 8 + tig * 2;
            const float m0 = mrow[c0] ? 0.f : 1.f;
            const float m1 = mrow[c0 + 1] ? 0.f : 1.f;
            slo += m0 * __expf(acc[i][j][0] * SCALE) + m1 * __expf(acc[i][j][1] * SCALE);
            shi += m0 * __expf(acc[i][j][2] * SCALE) + m1 * __expf(acc[i][j][3] * SCALE);
        }
        slo += __shfl_xor_sync(0xffffffffu, slo, 1);
        slo += __shfl_xor_sync(0xffffffffu, slo, 2);
        shi += __shfl_xor_sync(0xffffffffu, shi, 1);
        shi += __shfl_xor_sync(0xffffffffu, shi, 2);
        if (tig == 0) {
            atomicAdd(&sums[bq + wm + i * 16 + gid], slo);
            atomicAdd(&sums[bq + wm + i * 16 + gid + 8], shi);
        }
    }
}

// ---------------------------------------------------------------------------
// Kernel 3 (FULLY FUSED): recompute QK^T (tf32 mma) + exp/normalize/blend +
// single prob write (stcs) + P@V (tf32 mma).
// Block = one (b,h), 128 q rows, BOTH streams. 256 threads, 8 warps in m
// (16 q-rows each). k-tiles of 32 keys; K/V smem double-buffered with
// register prefetch; probs round-trip through a single smem buffer (2 syncs
// per iteration). Q fragments live in registers for the whole kernel.
// ---------------------------------------------------------------------------
// smem layout (u32 indices):
#define PSOFF(st)      ((st) * 4608)                       // probs  2 x 128x36
#define KSOFF(st,buf)  (9216 + ((st) * 2 + (buf)) * 1152)  // K tile 2x2 x 32x36
#define VSOFF(st,buf)  (13824 + ((st) * 2 + (buf)) * 1152) // V tile 2x2 x 32x36
#define MSKOFF         18432                               // mask   1024 f32
#define FUSED_SMEM     (19456 * 4)                         // 77824 bytes

__global__ __launch_bounds__(256, 2) void attn_fused_kernel(
    float* __restrict__ dout, const unsigned char* __restrict__ mask,
    const float* __restrict__ alpha_p, const float* __restrict__ beta_p)
{
    extern __shared__ uint32_t sm[];
    float* msk = reinterpret_cast<float*>(sm + MSKOFF);
    const int bh = blockIdx.y;
    const int b = bh >> 3, h = bh & 7;
    const int bq = blockIdx.x * 128;

    const int tid = threadIdx.x;
    const int wid = tid >> 5;
    const int lane = tid & 31;
    const int gid = lane >> 2;
    const int tig = lane & 3;
    const int sr0 = tid >> 3;          // 0..31
    const int sc0 = (tid & 7) * 4;     // 0,4,..28
    const int r = wid * 16;            // warp q-row base (local)

    const float* Q1 = g_qkv + ((size_t)(0) * 32 + bh) * (SDIM * DDIM);
    const float* K1 = g_qkv + ((size_t)(1) * 32 + bh) * (SDIM * DDIM);
    const float* V1 = g_qkv + ((size_t)(2) * 32 + bh) * (SDIM * DDIM);
    const float* Q2 = g_qkv + ((size_t)(3) * 32 + bh) * (SDIM * DDIM);
    const float* K2 = g_qkv + ((size_t)(4) * 32 + bh) * (SDIM * DDIM);
    const float* V2 = g_qkv + ((size_t)(5) * 32 + bh) * (SDIM * DDIM);
    float* S1 = dout + OFF_SHARED + ((size_t)bh * SDIM + bq) * SDIM;
    float* S2 = S1 + BHSS;

    // mask multiplier table
    for (int i = tid; i < SDIM; i += 256)
        msk[i] = mask[(size_t)b * SDIM + i] ? 0.f : 1.f;

    // ---- stage Q tiles into the PS region (temp), grab fragments ----
#pragma unroll
    for (int t = 0; t < 4; t++) {
        const int row = sr0 + 32 * t;
        float4 q1 = *reinterpret_cast<const float4*>(Q1 + (size_t)(bq + row) * 32 + sc0);
        float4 q2 = *reinterpret_cast<const float4*>(Q2 + (size_t)(bq + row) * 32 + sc0);
        uint32_t* p1 = sm + PSOFF(0) + row * 36 + sc0;
        p1[0] = f2tf(q1.x); p1[1] = f2tf(q1.y); p1[2] = f2tf(q1.z); p1[3] = f2tf(q1.w);
        uint32_t* p2 = sm + PSOFF(1) + row * 36 + sc0;
        p2[0] = f2tf(q2.x); p2[1] = f2tf(q2.y); p2[2] = f2tf(q2.z); p2[3] = f2tf(q2.w);
    }
    __syncthreads();

    uint32_t qf[2][4][4];
#pragma unroll
    for (int st = 0; st < 2; st++)
#pragma unroll
        for (int ks = 0; ks < 4; ks++) {
            const uint32_t* P = sm + PSOFF(st);
            qf[st][ks][0] = P[(r + gid) * 36 + 8 * ks + tig];
            qf[st][ks][1] = P[(r + gid + 8) * 36 + 8 * ks + tig];
            qf[st][ks][2] = P[(r + gid) * 36 + 8 * ks + tig + 4];
            qf[st][ks][3] = P[(r + gid + 8) * 36 + 8 * ks + tig + 4];
        }

    // blend coefficients folded with inverse sums (per thread's 2 rows)
    const float a = *alpha_p, bt = *beta_p;
    const int q0 = bq + r + gid;
    const float i1lo = 1.f / g_sums[(size_t)bh * SDIM + q0];
    const float i1hi = 1.f / g_sums[(size_t)bh * SDIM + q0 + 8];
    const float i2lo = 1.f / g_sums[(size_t)(32 + bh) * SDIM + q0];
    const float i2hi = 1.f / g_sums[(size_t)(32 + bh) * SDIM + q0 + 8];
    const float c1lo = (1.f - a) * i1lo, c2lo = a * i2lo;
    const float c1hi = (1.f - a) * i1hi, c2hi = a * i2hi;
    const float d2lo = (1.f - bt) * i2lo, d1lo = bt * i1lo;
    const float d2hi = (1.f - bt) * i2hi, d1hi = bt * i1hi;

    // stage K/V tile 0 into buffer 0
    {
        float4 x;
        x = *reinterpret_cast<const float4*>(K1 + (size_t)sr0 * 32 + sc0);
        uint32_t* p = sm + KSOFF(0, 0) + sr0 * 36 + sc0;
        p[0] = f2tf(x.x); p[1] = f2tf(x.y); p[2] = f2tf(x.z); p[3] = f2tf(x.w);
        x = *reinterpret_cast<const float4*>(K2 + (size_t)sr0 * 32 + sc0);
        p = sm + KSOFF(1, 0) + sr0 * 36 + sc0;
        p[0] = f2tf(x.x); p[1] = f2tf(x.y); p[2] = f2tf(x.z); p[3] = f2tf(x.w);
        x = *reinterpret_cast<const float4*>(V1 + (size_t)sr0 * 32 + sc0);
        p = sm + VSOFF(0, 0) + sr0 * 36 + sc0;
        p[0] = f2tf(x.x); p[1] = f2tf(x.y); p[2] = f2tf(x.z); p[3] = f2tf(x.w);
        x = *reinterpret_cast<const float4*>(V2 + (size_t)sr0 * 32 + sc0);
        p = sm + VSOFF(1, 0) + sr0 * 36 + sc0;
        p[0] = f2tf(x.x); p[1] = f2tf(x.y); p[2] = f2tf(x.z); p[3] = f2tf(x.w);
    }
    __syncthreads();

    float o[2][4][4] = {};

    for (int kt = 0; kt < 32; kt++) {
        const int cur = kt & 1;

        // prefetch next K/V tiles into registers
        float4 k1n, k2n, v1n, v2n;
        if (kt < 31) {
            const int k0 = (kt + 1) * 32;
            k1n = *reinterpret_cast<const float4*>(K1 + (size_t)(k0 + sr0) * 32 + sc0);
            k2n = *reinterpret_cast<const float4*>(K2 + (size_t)(k0 + sr0) * 32 + sc0);
            v1n = *reinterpret_cast<const float4*>(V1 + (size_t)(k0 + sr0) * 32 + sc0);
            v2n = *reinterpret_cast<const float4*>(V2 + (size_t)(k0 + sr0) * 32 + sc0);
        }

        // ---- scores + probs, per 8-key group j ----
        const uint32_t* KA = sm + KSOFF(0, cur);
        const uint32_t* KB = sm + KSOFF(1, cur);
#pragma unroll
        for (int j = 0; j < 4; j++) {
            float sA[4] = {}, sB[4] = {};
#pragma unroll
            for (int ks = 0; ks < 4; ks++) {
                uint32_t bf[2];
                bf[0] = KA[(j * 8 + gid) * 36 + 8 * ks + tig];
                bf[1] = KA[(j * 8 + gid) * 36 + 8 * ks + tig + 4];
                mma_tf32(sA, qf[0][ks], bf);
                bf[0] = KB[(j * 8 + gid) * 36 + 8 * ks + tig];
                bf[1] = KB[(j * 8 + gid) * 36 + 8 * ks + tig + 4];
                mma_tf32(sB, qf[1][ks], bf);
            }
            const int c0 = kt * 32 + j * 8 + tig * 2;
            const float m0 = msk[c0], m1 = msk[c0 + 1];
            const float e1x = m0 * __expf(sA[0] * SCALE), e1y = m1 * __expf(sA[1] * SCALE);
            const float e1z = m0 * __expf(sA[2] * SCALE), e1w = m1 * __expf(sA[3] * SCALE);
            const float e2x = m0 * __expf(sB[0] * SCALE), e2y = m1 * __expf(sB[1] * SCALE);
            const float e2z = m0 * __expf(sB[2] * SCALE), e2w = m1 * __expf(sB[3] * SCALE);
            const float p1x = c1lo * e1x + c2lo * e2x, p1y = c1lo * e1y + c2lo * e2y;
            const float p1z = c1hi * e1z + c2hi * e2z, p1w = c1hi * e1w + c2hi * e2w;
            const float p2x = d2lo * e2x + d1lo * e1x, p2y = d2lo * e2y + d1lo * e1y;
            const float p2z = d2hi * e2z + d1hi * e1z, p2w = d2hi * e2w + d1hi * e1w;
            // single DRAM write of the blended probs
            __stcs(reinterpret_cast<float2*>(S1 + (size_t)(r + gid) * SDIM + c0), make_float2(p1x, p1y));
            __stcs(reinterpret_cast<float2*>(S1 + (size_t)(r + gid + 8) * SDIM + c0), make_float2(p1z, p1w));
            __stcs(reinterpret_cast<float2*>(S2 + (size_t)(r + gid) * SDIM + c0), make_float2(p2x, p2y));
            __stcs(reinterpret_cast<float2*>(S2 + (size_t)(r + gid + 8) * SDIM + c0), make_float2(p2z, p2w));
            // tf32 probs into smem for the PV mma (local cols)
            const int cl = j * 8 + tig * 2;
            uint32_t* P1 = sm + PSOFF(0);
            uint32_t* P2 = sm + PSOFF(1);
            P1[(r + gid) * 36 + cl] = f2tf(p1x);     P1[(r + gid) * 36 + cl + 1] = f2tf(p1y);
            P1[(r + gid + 8) * 36 + cl] = f2tf(p1z); P1[(r + gid + 8) * 36 + cl + 1] = f2tf(p1w);
            P2[(r + gid) * 36 + cl] = f2tf(p2x);     P2[(r + gid) * 36 + cl + 1] = f2tf(p2y);
            P2[(r + gid + 8) * 36 + cl] = f2tf(p2z); P2[(r + gid + 8) * 36 + cl + 1] = f2tf(p2w);
        }

        // stash prefetched K/V into the other buffer
        if (kt < 31) {
            uint32_t* p;
            p = sm + KSOFF(0, cur ^ 1) + sr0 * 36 + sc0;
            p[0] = f2tf(k1n.x); p[1] = f2tf(k1n.y); p[2] = f2tf(k1n.z); p[3] = f2tf(k1n.w);
            p = sm + KSOFF(1, cur ^ 1) + sr0 * 36 + sc0;
            p[0] = f2tf(k2n.x); p[1] = f2tf(k2n.y); p[2] = f2tf(k2n.z); p[3] = f2tf(k2n.w);
            p = sm + VSOFF(0, cur ^ 1) + sr0 * 36 + sc0;
            p[0] = f2tf(v1n.x); p[1] = f2tf(v1n.y); p[2] = f2tf(v1n.z); p[3] = f2tf(v1n.w);
            p = sm + VSOFF(1, cur ^ 1) + sr0 * 36 + sc0;
            p[0] = f2tf(v2n.x); p[1] = f2tf(v2n.y); p[2] = f2tf(v2n.z); p[3] = f2tf(v2n.w);
        }
        __syncthreads();

        // ---- PV mma on this key tile, both streams ----
#pragma unroll
        for (int st = 0; st < 2; st++) {
            const uint32_t* P = sm + PSOFF(st);
            const uint32_t* Vt = sm + VSOFF(st, cur);
#pragma unroll
            for (int ks = 0; ks < 4; ks++) {
                const int k8 = ks * 8;
                uint32_t av[4];
                av[0] = P[(r + gid) * 36 + k8 + tig];
                av[1] = P[(r + gid + 8) * 36 + k8 + tig];
                av[2] = P[(r + gid) * 36 + k8 + tig + 4];
                av[3] = P[(r + gid + 8) * 36 + k8 + tig + 4];
#pragma unroll
                for (int j2 = 0; j2 < 4; j2++) {
                    uint32_t bf[2];
                    bf[0] = Vt[(k8 + tig) * 36 + j2 * 8 + gid];
                    bf[1] = Vt[(k8 + tig + 4) * 36 + j2 * 8 + gid];
                    mma_tf32(o[st][j2], av, bf);
                }
            }
        }
        __syncthreads();   // protect PS reuse next iteration
    }

    // epilogue: O -> g_ocat
#pragma unroll
    for (int st = 0; st < 2; st++) {
#pragma unroll
        for (int j2 = 0; j2 < 4; j2++) {
            const int d0 = j2 * 8 + tig * 2;
            float* o0 = &g_ocat[((size_t)(st * 4 + b) * SDIM + q0) * EDIM + h * 32 + d0];
            float* o1 = &g_ocat[((size_t)(st * 4 + b) * SDIM + q0 + 8) * EDIM + h * 32 + d0];
            *reinterpret_cast<float2*>(o0) = make_float2(o[st][j2][0], o[st][j2][1]);
            *reinterpret_cast<float2*>(o1) = make_float2(o[st][j2][2], o[st][j2][3]);
        }
    }
}

// ---------------------------------------------------------------------------
// Kernel 4: batched output projection (fp32, accuracy headroom). grid.z = st.
// ---------------------------------------------------------------------------
struct OutArgs {
    const float* w[2];
    const float* b[2];
};

__global__ __launch_bounds__(256) void outproj_kernel(OutArgs args, float* __restrict__ dout)
{
    __shared__ float As[16][64];
    __shared__ float Bs[16][64];
    const int st = blockIdx.z;
    const float* W = args.w[st];
    const float* bias = args.b[st];
    float* out = dout + (size_t)st * (SDIM * BDIM * EDIM);

    const int bm = blockIdx.y * 64;
    const int bn = blockIdx.x * 64;
    const int tid = threadIdx.x;
    const int tx = tid & 15;
    const int ty = tid >> 4;
    const float* A = g_ocat + (size_t)st * (BDIM * SDIM * EDIM);

    float acc[4][4] = {};
    const int lrow = tid >> 2;
    const int lcol = (tid & 3) * 4;

    for (int k0 = 0; k0 < 256; k0 += 16) {
        float4 va = *reinterpret_cast<const float4*>(A + (size_t)(bm + lrow) * 256 + k0 + lcol);
        float4 vb = *reinterpret_cast<const float4*>(W + (size_t)(bn + lrow) * 256 + k0 + lcol);
        As[lcol + 0][lrow] = va.x; As[lcol + 1][lrow] = va.y;
        As[lcol + 2][lrow] = va.z; As[lcol + 3][lrow] = va.w;
        Bs[lcol + 0][lrow] = vb.x; Bs[lcol + 1][lrow] = vb.y;
        Bs[lcol + 2][lrow] = vb.z; Bs[lcol + 3][lrow] = vb.w;
        __syncthreads();
#pragma unroll
        for (int kk = 0; kk < 16; kk++) {
            float a[4], b[4];
#pragma unroll
            for (int i = 0; i < 4; i++) a[i] = As[kk][ty * 4 + i];
#pragma unroll
            for (int j = 0; j < 4; j++) b[j] = Bs[kk][tx * 4 + j];
#pragma unroll
            for (int i = 0; i < 4; i++)
#pragma unroll
                for (int j = 0; j < 4; j++) acc[i][j] += a[i] * b[j];
        }
        __syncthreads();
    }

#pragma unroll
    for (int i = 0; i < 4; i++) {
        const int m = bm + ty * 4 + i;     // m = b*1024 + s
        const int b = m >> 10;
        const int s = m & 1023;
#pragma unroll
        for (int j = 0; j < 4; j++) {
            const int n = bn + tx * 4 + j;
            out[(size_t)(s * 4 + b) * 256 + n] = acc[i][j] + bias[n];
        }
    }
}

// ---------------------------------------------------------------------------
extern "C" void kernel_launch(void* const* d_in, const int* in_sizes, int n_in,
                              void* d_out, int out_size)
{
    const unsigned char* mask = (const unsigned char*)d_in[6];
    const float* alpha = (const float*)d_in[15];
    const float* beta  = (const float*)d_in[16];
    float* out = (float*)d_out;

    cudaFuncSetAttribute(attn_fused_kernel,
                         cudaFuncAttributeMaxDynamicSharedMemorySize, FUSED_SMEM);

    // 0) zero exp-sum accumulators
    zero_sums_kernel<<<256, 256>>>();

    // 1) all six QKV projections in one launch (tf32 mma)
    ProjArgs pa;
    for (int i = 0; i < 6; i++) pa.x[i] = (const float*)d_in[i];
    pa.w[0] = (const float*)d_in[7];  pa.b[0] = (const float*)d_in[8];
    pa.w[1] = (const float*)d_in[11]; pa.b[1] = (const float*)d_in[12];
    proj_tf32_kernel<<<dim3(2, 32, 6), 256>>>(pa);

    // 2) exp-sum stats only (no score writes)
    sums_kernel<<<dim3(8, 8, 64), 256>>>(mask);

    // 3) fully fused: recompute scores + normalize + blend + prob write + P@V
    attn_fused_kernel<<<dim3(8, 32), 256, FUSED_SMEM>>>(out, mask, alpha, beta);

    // 4) both output projections in one launch (fp32)
    OutArgs oa;
    oa.w[0] = (const float*)d_in[9];  oa.b[0] = (const float*)d_in[10];
    oa.w[1] = (const float*)d_in[13]; oa.b[1] = (const float*)d_in[14];
    outproj_kernel<<<dim3(4, 64, 2), 256>>>(oa, out);
}

// round 9
// speedup vs baseline: 1.8942x; 1.0560x over previous
#include <cuda_runtime.h>
#include <cuda_bf16.h>
#include <math_constants.h>
#include <cstdint>

// Problem constants
#define SDIM 1024
#define BDIM 4
#define EDIM 256
#define HDIM 8
#define DDIM 32

// d_out layout: out_rgb [S,B,E], out_dpt [S,B,E], shared_rgb [B,H,S,S], shared_dpt [B,H,S,S]
#define OFF_OUT_RGB  0
#define OFF_OUT_DPT  (SDIM*BDIM*EDIM)              // 1048576
#define OFF_SHARED   (2*SDIM*BDIM*EDIM)            // 2097152
#define BHSS         ((size_t)BDIM*HDIM*SDIM*SDIM) // 33554432

#define SCALE 0.17677669529663687f   // 1/sqrt(32)

// Scratch
__device__ float g_qkv[6 * BDIM * HDIM * SDIM * DDIM];   // 25 MB
__device__ float g_ocat[2 * BDIM * SDIM * EDIM];         // 8 MB
__device__ float g_sums[2 * 32 * SDIM];                  // exp-sums per (st,bh,q)

// ---------------------------------------------------------------------------
// tf32 helpers (mma.sync m16n8k8, fp32 accum)
// ---------------------------------------------------------------------------
__device__ __forceinline__ uint32_t f2tf(float f) {
    uint32_t u;
    asm("cvt.rna.tf32.f32 %0, %1;" : "=r"(u) : "f"(f));
    return u;
}

__device__ __forceinline__ void mma_tf32(float* d, const uint32_t* a, const uint32_t* b) {
    asm volatile(
        "mma.sync.aligned.m16n8k8.row.col.f32.tf32.tf32.f32 "
        "{%0,%1,%2,%3}, {%4,%5,%6,%7}, {%8,%9}, {%0,%1,%2,%3};"
        : "+f"(d[0]), "+f"(d[1]), "+f"(d[2]), "+f"(d[3])
        : "r"(a[0]), "r"(a[1]), "r"(a[2]), "r"(a[3]),
          "r"(b[0]), "r"(b[1]));
}

// Convert a score C-fragment (16x8 tile: thread holds cols 2*tig, 2*tig+1 of
// rows gid, gid+8) into a PV A-fragment (thread needs cols tig, tig+4) via
// warp shuffles. No smem, no barrier.
__device__ __forceinline__ void c2a(uint32_t* av, float c0, float c1,
                                    float c2, float c3, int gid, int tig)
{
    const unsigned FULL = 0xffffffffu;
    const int base = gid * 4 + (tig >> 1);
    float x0 = __shfl_sync(FULL, c0, base);
    float x1 = __shfl_sync(FULL, c1, base);
    float y0 = __shfl_sync(FULL, c2, base);
    float y1 = __shfl_sync(FULL, c3, base);
    float z0 = __shfl_sync(FULL, c0, base + 2);
    float z1 = __shfl_sync(FULL, c1, base + 2);
    float w0 = __shfl_sync(FULL, c2, base + 2);
    float w1 = __shfl_sync(FULL, c3, base + 2);
    const bool odd = tig & 1;
    av[0] = f2tf(odd ? x1 : x0);
    av[1] = f2tf(odd ? y1 : y0);
    av[2] = f2tf(odd ? z1 : z0);
    av[3] = f2tf(odd ? w1 : w0);
}

__device__ __forceinline__ void stage4(uint32_t* dst, float4 v) {
    uint4 u = make_uint4(f2tf(v.x), f2tf(v.y), f2tf(v.z), f2tf(v.w));
    *reinterpret_cast<uint4*>(dst) = u;
}

// ---------------------------------------------------------------------------
// Kernel 0: zero the sums accumulator (graph-replayed every launch)
// ---------------------------------------------------------------------------
__global__ void zero_sums_kernel() {
    g_sums[blockIdx.x * 256 + threadIdx.x] = 0.f;
}

// ---------------------------------------------------------------------------
// Kernel 1: batched QKV projection via tf32 mma. grid.z = proj id 0..5.
// ---------------------------------------------------------------------------
struct ProjArgs {
    const float* x[6];
    const float* w[2];
    const float* b[2];
};

__global__ __launch_bounds__(256) void proj_tf32_kernel(ProjArgs args)
{
    __shared__ uint32_t As[128][36];
    __shared__ uint32_t Bs[128][36];
    const int proj = blockIdx.z;
    const int st = proj / 3;
    const int wsel = proj - st * 3;
    const float* x = args.x[proj];
    const float* W = args.w[st] + (size_t)wsel * 256 * 256;
    const float* bias = args.b[st] + wsel * 256;

    const int bm = blockIdx.y * 128;
    const int bn = blockIdx.x * 128;
    const int tid = threadIdx.x;
    const int wid = tid >> 5;
    const int lane = tid & 31;
    const int gid = lane >> 2;
    const int tig = lane & 3;
    const int wm = (wid & 3) * 32;
    const int wn = (wid >> 2) * 64;

    const int sr0 = tid >> 3;            // 0..31, +32*t
    const int sc0 = (tid & 7) * 4;       // 0,4,..28

    float4 pa[4], pb[4];
#pragma unroll
    for (int t = 0; t < 4; t++) {
        pa[t] = *reinterpret_cast<const float4*>(x + (size_t)(bm + sr0 + t * 32) * 256 + sc0);
        pb[t] = *reinterpret_cast<const float4*>(W + (size_t)(bn + sr0 + t * 32) * 256 + sc0);
    }

    float acc[2][8][4] = {};

    for (int kt = 0; kt < 8; kt++) {
#pragma unroll
        for (int t = 0; t < 4; t++) {
            const int r = sr0 + t * 32;
            As[r][sc0 + 0] = f2tf(pa[t].x); As[r][sc0 + 1] = f2tf(pa[t].y);
            As[r][sc0 + 2] = f2tf(pa[t].z); As[r][sc0 + 3] = f2tf(pa[t].w);
            Bs[r][sc0 + 0] = f2tf(pb[t].x); Bs[r][sc0 + 1] = f2tf(pb[t].y);
            Bs[r][sc0 + 2] = f2tf(pb[t].z); Bs[r][sc0 + 3] = f2tf(pb[t].w);
        }
        __syncthreads();

        if (kt < 7) {
            const int k0 = (kt + 1) * 32;
#pragma unroll
            for (int t = 0; t < 4; t++) {
                pa[t] = *reinterpret_cast<const float4*>(x + (size_t)(bm + sr0 + t * 32) * 256 + k0 + sc0);
                pb[t] = *reinterpret_cast<const float4*>(W + (size_t)(bn + sr0 + t * 32) * 256 + k0 + sc0);
            }
        }

#pragma unroll
        for (int kc = 0; kc < 4; kc++) {
            const int k8 = kc * 8;
            uint32_t a[2][4], b[8][2];
#pragma unroll
            for (int i = 0; i < 2; i++) {
                const int r = wm + i * 16;
                a[i][0] = As[r + gid][k8 + tig];
                a[i][1] = As[r + gid + 8][k8 + tig];
                a[i][2] = As[r + gid][k8 + tig + 4];
                a[i][3] = As[r + gid + 8][k8 + tig + 4];
            }
#pragma unroll
            for (int j = 0; j < 8; j++) {
                const int c = wn + j * 8;
                b[j][0] = Bs[c + gid][k8 + tig];
                b[j][1] = Bs[c + gid][k8 + tig + 4];
            }
#pragma unroll
            for (int i = 0; i < 2; i++)
#pragma unroll
                for (int j = 0; j < 8; j++)
                    mma_tf32(acc[i][j], a[i], b[j]);
        }
        __syncthreads();
    }

#pragma unroll
    for (int i = 0; i < 2; i++) {
        const int m0 = bm + wm + i * 16 + gid;
        const int s0 = m0 >> 2, b0 = m0 & 3;
        const int m1 = m0 + 8;
        const int s1 = m1 >> 2, b1 = m1 & 3;
#pragma unroll
        for (int j = 0; j < 8; j++) {
            const int c0 = bn + wn + j * 8 + tig * 2;
            const int h = c0 >> 5;
            const int d = c0 & 31;
            const float bv0 = bias[c0], bv1 = bias[c0 + 1];
            float* p0 = &g_qkv[(((size_t)(proj * 4 + b0) * 8 + h) * 1024 + s0) * 32 + d];
            float* p1 = &g_qkv[(((size_t)(proj * 4 + b1) * 8 + h) * 1024 + s1) * 32 + d];
            *reinterpret_cast<float2*>(p0) = make_float2(acc[i][j][0] + bv0, acc[i][j][1] + bv1);
            *reinterpret_cast<float2*>(p1) = make_float2(acc[i][j][2] + bv0, acc[i][j][3] + bv1);
        }
    }
}

// ---------------------------------------------------------------------------
// Kernel 2: exp-sum stats only (no score writes). QK^T via tf32 mma,
// per-row sum of exp(scaled score) with mask, atomicAdd into g_sums.
// Accumulation order matches attn_fused_kernel exactly -> identical values.
// ---------------------------------------------------------------------------
__global__ __launch_bounds__(256) void sums_kernel(const unsigned char* __restrict__ mask)
{
    __shared__ uint32_t Qs[128][36];
    __shared__ uint32_t Ks[128][36];
    const int z = blockIdx.z;
    const int st = z >> 5;
    const int bh = z & 31;
    const int bq = blockIdx.y * 128;
    const int bk = blockIdx.x * 128;

    const float* Q = g_qkv + ((size_t)(st * 3 + 0) * 32 + bh) * (SDIM * DDIM);
    const float* K = g_qkv + ((size_t)(st * 3 + 1) * 32 + bh) * (SDIM * DDIM);

    const int tid = threadIdx.x;
    for (int i = tid * 4; i < 128 * 32; i += 1024) {
        const int r = i >> 5, c = i & 31;
        float4 q4 = *reinterpret_cast<const float4*>(Q + (size_t)(bq + r) * 32 + c);
        float4 k4 = *reinterpret_cast<const float4*>(K + (size_t)(bk + r) * 32 + c);
        Qs[r][c + 0] = f2tf(q4.x); Qs[r][c + 1] = f2tf(q4.y);
        Qs[r][c + 2] = f2tf(q4.z); Qs[r][c + 3] = f2tf(q4.w);
        Ks[r][c + 0] = f2tf(k4.x); Ks[r][c + 1] = f2tf(k4.y);
        Ks[r][c + 2] = f2tf(k4.z); Ks[r][c + 3] = f2tf(k4.w);
    }
    __syncthreads();

    const int wid = tid >> 5;
    const int lane = tid & 31;
    const int gid = lane >> 2;
    const int tig = lane & 3;
    const int wm = (wid & 3) * 32;
    const int wn = (wid >> 2) * 64;

    float acc[2][8][4] = {};
#pragma unroll
    for (int kc = 0; kc < 4; kc++) {
        const int k0 = kc * 8;
        uint32_t a[2][4], b[8][2];
#pragma unroll
        for (int i = 0; i < 2; i++) {
            const int r = wm + i * 16;
            a[i][0] = Qs[r + gid][k0 + tig];
            a[i][1] = Qs[r + gid + 8][k0 + tig];
            a[i][2] = Qs[r + gid][k0 + tig + 4];
            a[i][3] = Qs[r + gid + 8][k0 + tig + 4];
        }
#pragma unroll
        for (int j = 0; j < 8; j++) {
            const int c = wn + j * 8;
            b[j][0] = Ks[c + gid][k0 + tig];
            b[j][1] = Ks[c + gid][k0 + tig + 4];
        }
#pragma unroll
        for (int i = 0; i < 2; i++)
#pragma unroll
            for (int j = 0; j < 8; j++)
                mma_tf32(acc[i][j], a[i], b[j]);
    }

    const unsigned char* mrow = mask + (size_t)(bh >> 3) * SDIM;
    float* sums = g_sums + (size_t)z * SDIM;
#pragma unroll
    for (int i = 0; i < 2; i++) {
        float slo = 0.f, shi = 0.f;
#pragma unroll
        for (int j = 0; j < 8; j++) {
            const int c0 = bk + wn + j * 8 + tig * 2;
            const float m0 = mrow[c0] ? 0.f : 1.f;
            const float m1 = mrow[c0 + 1] ? 0.f : 1.f;
            slo += m0 * __expf(acc[i][j][0] * SCALE) + m1 * __expf(acc[i][j][1] * SCALE);
            shi += m0 * __expf(acc[i][j][2] * SCALE) + m1 * __expf(acc[i][j][3] * SCALE);
        }
        slo += __shfl_xor_sync(0xffffffffu, slo, 1);
        slo += __shfl_xor_sync(0xffffffffu, slo, 2);
        shi += __shfl_xor_sync(0xffffffffu, shi, 1);
        shi += __shfl_xor_sync(0xffffffffu, shi, 2);
        if (tig == 0) {
            atomicAdd(&sums[bq + wm + i * 16 + gid], slo);
            atomicAdd(&sums[bq + wm + i * 16 + gid + 8], shi);
        }
    }
}

// ---------------------------------------------------------------------------
// Kernel 3 (FULLY FUSED, register-resident probs):
// recompute QK^T (tf32 mma) + exp/normalize/blend + single prob write (stcs)
// + shuffle C->A fragment + P@V (tf32 mma), all without a probs smem buffer.
// Block = one (b,h), 128 q rows, BOTH streams. 256 threads, 8 warps in m.
// k-tiles of 32 keys; K/V smem double-buffered (uint4 staging); ONE sync/tile.
// ---------------------------------------------------------------------------
// smem layout (u32 indices):
#define KSOFF(st,buf)  (((st) * 2 + (buf)) * 1152)         // K tiles 2x2 x 32x36
#define VSOFF(st,buf)  (4608 + ((st) * 2 + (buf)) * 1152)  // V tiles 2x2 x 32x36
#define MSKOFF         9216                                // mask 1024 f32
#define FUSED_SMEM     (10240 * 4)                         // 40960 bytes

__global__ __launch_bounds__(256, 2) void attn_fused_kernel(
    float* __restrict__ dout, const unsigned char* __restrict__ mask,
    const float* __restrict__ alpha_p, const float* __restrict__ beta_p)
{
    extern __shared__ uint32_t sm[];
    float* msk = reinterpret_cast<float*>(sm + MSKOFF);
    const int bh = blockIdx.y;
    const int b = bh >> 3, h = bh & 7;
    const int bq = blockIdx.x * 128;

    const int tid = threadIdx.x;
    const int wid = tid >> 5;
    const int lane = tid & 31;
    const int gid = lane >> 2;
    const int tig = lane & 3;
    const int sr0 = tid >> 3;          // 0..31
    const int sc0 = (tid & 7) * 4;     // 0,4,..28
    const int r = wid * 16;            // warp q-row base (local)

    const float* Q1 = g_qkv + ((size_t)(0) * 32 + bh) * (SDIM * DDIM);
    const float* K1 = g_qkv + ((size_t)(1) * 32 + bh) * (SDIM * DDIM);
    const float* V1 = g_qkv + ((size_t)(2) * 32 + bh) * (SDIM * DDIM);
    const float* Q2 = g_qkv + ((size_t)(3) * 32 + bh) * (SDIM * DDIM);
    const float* K2 = g_qkv + ((size_t)(4) * 32 + bh) * (SDIM * DDIM);
    const float* V2 = g_qkv + ((size_t)(5) * 32 + bh) * (SDIM * DDIM);
    float* S1 = dout + OFF_SHARED + ((size_t)bh * SDIM + bq) * SDIM;
    float* S2 = S1 + BHSS;

    // mask multiplier table
    for (int i = tid; i < SDIM; i += 256)
        msk[i] = mask[(size_t)b * SDIM + i] ? 0.f : 1.f;

    // Q fragments straight from gmem (one-time prologue)
    uint32_t qf[2][4][4];
#pragma unroll
    for (int st = 0; st < 2; st++) {
        const float* Q = st ? Q2 : Q1;
#pragma unroll
        for (int ks = 0; ks < 4; ks++) {
            qf[st][ks][0] = f2tf(Q[(size_t)(bq + r + gid) * 32 + 8 * ks + tig]);
            qf[st][ks][1] = f2tf(Q[(size_t)(bq + r + gid + 8) * 32 + 8 * ks + tig]);
            qf[st][ks][2] = f2tf(Q[(size_t)(bq + r + gid) * 32 + 8 * ks + tig + 4]);
            qf[st][ks][3] = f2tf(Q[(size_t)(bq + r + gid + 8) * 32 + 8 * ks + tig + 4]);
        }
    }

    // blend coefficients folded with inverse sums (per thread's 2 rows)
    const float a = *alpha_p, bt = *beta_p;
    const int q0 = bq + r + gid;
    const float i1lo = 1.f / g_sums[(size_t)bh * SDIM + q0];
    const float i1hi = 1.f / g_sums[(size_t)bh * SDIM + q0 + 8];
    const float i2lo = 1.f / g_sums[(size_t)(32 + bh) * SDIM + q0];
    const float i2hi = 1.f / g_sums[(size_t)(32 + bh) * SDIM + q0 + 8];
    const float c1lo = (1.f - a) * i1lo, c2lo = a * i2lo;
    const float c1hi = (1.f - a) * i1hi, c2hi = a * i2hi;
    const float d2lo = (1.f - bt) * i2lo, d1lo = bt * i1lo;
    const float d2hi = (1.f - bt) * i2hi, d1hi = bt * i1hi;

    // stage K/V tile 0 into buffer 0 (vectorized)
    stage4(sm + KSOFF(0, 0) + sr0 * 36 + sc0,
           *reinterpret_cast<const float4*>(K1 + (size_t)sr0 * 32 + sc0));
    stage4(sm + KSOFF(1, 0) + sr0 * 36 + sc0,
           *reinterpret_cast<const float4*>(K2 + (size_t)sr0 * 32 + sc0));
    stage4(sm + VSOFF(0, 0) + sr0 * 36 + sc0,
           *reinterpret_cast<const float4*>(V1 + (size_t)sr0 * 32 + sc0));
    stage4(sm + VSOFF(1, 0) + sr0 * 36 + sc0,
           *reinterpret_cast<const float4*>(V2 + (size_t)sr0 * 32 + sc0));
    __syncthreads();

    float o[2][4][4] = {};

    for (int kt = 0; kt < 32; kt++) {
        const int cur = kt & 1;

        // prefetch next K/V tiles into registers
        float4 k1n, k2n, v1n, v2n;
        if (kt < 31) {
            const int k0 = (kt + 1) * 32;
            k1n = *reinterpret_cast<const float4*>(K1 + (size_t)(k0 + sr0) * 32 + sc0);
            k2n = *reinterpret_cast<const float4*>(K2 + (size_t)(k0 + sr0) * 32 + sc0);
            v1n = *reinterpret_cast<const float4*>(V1 + (size_t)(k0 + sr0) * 32 + sc0);
            v2n = *reinterpret_cast<const float4*>(V2 + (size_t)(k0 + sr0) * 32 + sc0);
        }

        const uint32_t* KA = sm + KSOFF(0, cur);
        const uint32_t* KB = sm + KSOFF(1, cur);
        const uint32_t* VA = sm + VSOFF(0, cur);
        const uint32_t* VB = sm + VSOFF(1, cur);

        // ---- per 8-key group: scores -> probs -> shuffle -> PV mma ----
#pragma unroll
        for (int j = 0; j < 4; j++) {
            float sA[4] = {}, sB[4] = {};
#pragma unroll
            for (int ks = 0; ks < 4; ks++) {
                uint32_t bf[2];
                bf[0] = KA[(j * 8 + gid) * 36 + 8 * ks + tig];
                bf[1] = KA[(j * 8 + gid) * 36 + 8 * ks + tig + 4];
                mma_tf32(sA, qf[0][ks], bf);
                bf[0] = KB[(j * 8 + gid) * 36 + 8 * ks + tig];
                bf[1] = KB[(j * 8 + gid) * 36 + 8 * ks + tig + 4];
                mma_tf32(sB, qf[1][ks], bf);
            }
            const int c0 = kt * 32 + j * 8 + tig * 2;
            const float m0 = msk[c0], m1 = msk[c0 + 1];
            const float e1x = m0 * __expf(sA[0] * SCALE), e1y = m1 * __expf(sA[1] * SCALE);
            const float e1z = m0 * __expf(sA[2] * SCALE), e1w = m1 * __expf(sA[3] * SCALE);
            const float e2x = m0 * __expf(sB[0] * SCALE), e2y = m1 * __expf(sB[1] * SCALE);
            const float e2z = m0 * __expf(sB[2] * SCALE), e2w = m1 * __expf(sB[3] * SCALE);
            const float p1x = c1lo * e1x + c2lo * e2x, p1y = c1lo * e1y + c2lo * e2y;
            const float p1z = c1hi * e1z + c2hi * e2z, p1w = c1hi * e1w + c2hi * e2w;
            const float p2x = d2lo * e2x + d1lo * e1x, p2y = d2lo * e2y + d1lo * e1y;
            const float p2z = d2hi * e2z + d1hi * e1z, p2w = d2hi * e2w + d1hi * e1w;
            // single DRAM write of the blended probs
            __stcs(reinterpret_cast<float2*>(S1 + (size_t)(r + gid) * SDIM + c0), make_float2(p1x, p1y));
            __stcs(reinterpret_cast<float2*>(S1 + (size_t)(r + gid + 8) * SDIM + c0), make_float2(p1z, p1w));
            __stcs(reinterpret_cast<float2*>(S2 + (size_t)(r + gid) * SDIM + c0), make_float2(p2x, p2y));
            __stcs(reinterpret_cast<float2*>(S2 + (size_t)(r + gid + 8) * SDIM + c0), make_float2(p2z, p2w));

            // C-fragment -> A-fragment in registers, then PV mma right away
            uint32_t avA[4], avB[4];
            c2a(avA, p1x, p1y, p1z, p1w, gid, tig);
            c2a(avB, p2x, p2y, p2z, p2w, gid, tig);
#pragma unroll
            for (int j2 = 0; j2 < 4; j2++) {
                uint32_t bf[2];
                bf[0] = VA[(j * 8 + tig) * 36 + j2 * 8 + gid];
                bf[1] = VA[(j * 8 + tig + 4) * 36 + j2 * 8 + gid];
                mma_tf32(o[0][j2], avA, bf);
                bf[0] = VB[(j * 8 + tig) * 36 + j2 * 8 + gid];
                bf[1] = VB[(j * 8 + tig + 4) * 36 + j2 * 8 + gid];
                mma_tf32(o[1][j2], avB, bf);
            }
        }

        // stash prefetched K/V into the other buffer (vectorized)
        if (kt < 31) {
            stage4(sm + KSOFF(0, cur ^ 1) + sr0 * 36 + sc0, k1n);
            stage4(sm + KSOFF(1, cur ^ 1) + sr0 * 36 + sc0, k2n);
            stage4(sm + VSOFF(0, cur ^ 1) + sr0 * 36 + sc0, v1n);
            stage4(sm + VSOFF(1, cur ^ 1) + sr0 * 36 + sc0, v2n);
        }
        __syncthreads();
    }

    // epilogue: O -> g_ocat
#pragma unroll
    for (int st = 0; st < 2; st++) {
#pragma unroll
        for (int j2 = 0; j2 < 4; j2++) {
            const int d0 = j2 * 8 + tig * 2;
            float* o0 = &g_ocat[((size_t)(st * 4 + b) * SDIM + q0) * EDIM + h * 32 + d0];
            float* o1 = &g_ocat[((size_t)(st * 4 + b) * SDIM + q0 + 8) * EDIM + h * 32 + d0];
            *reinterpret_cast<float2*>(o0) = make_float2(o[st][j2][0], o[st][j2][1]);
            *reinterpret_cast<float2*>(o1) = make_float2(o[st][j2][2], o[st][j2][3]);
        }
    }
}

// ---------------------------------------------------------------------------
// Kernel 4: batched output projection (fp32, accuracy headroom). grid.z = st.
// ---------------------------------------------------------------------------
struct OutArgs {
    const float* w[2];
    const float* b[2];
};

__global__ __launch_bounds__(256) void outproj_kernel(OutArgs args, float* __restrict__ dout)
{
    __shared__ float As[16][64];
    __shared__ float Bs[16][64];
    const int st = blockIdx.z;
    const float* W = args.w[st];
    const float* bias = args.b[st];
    float* out = dout + (size_t)st * (SDIM * BDIM * EDIM);

    const int bm = blockIdx.y * 64;
    const int bn = blockIdx.x * 64;
    const int tid = threadIdx.x;
    const int tx = tid & 15;
    const int ty = tid >> 4;
    const float* A = g_ocat + (size_t)st * (BDIM * SDIM * EDIM);

    float acc[4][4] = {};
    const int lrow = tid >> 2;
    const int lcol = (tid & 3) * 4;

    for (int k0 = 0; k0 < 256; k0 += 16) {
        float4 va = *reinterpret_cast<const float4*>(A + (size_t)(bm + lrow) * 256 + k0 + lcol);
        float4 vb = *reinterpret_cast<const float4*>(W + (size_t)(bn + lrow) * 256 + k0 + lcol);
        As[lcol + 0][lrow] = va.x; As[lcol + 1][lrow] = va.y;
        As[lcol + 2][lrow] = va.z; As[lcol + 3][lrow] = va.w;
        Bs[lcol + 0][lrow] = vb.x; Bs[lcol + 1][lrow] = vb.y;
        Bs[lcol + 2][lrow] = vb.z; Bs[lcol + 3][lrow] = vb.w;
        __syncthreads();
#pragma unroll
        for (int kk = 0; kk < 16; kk++) {
            float a[4], b[4];
#pragma unroll
            for (int i = 0; i < 4; i++) a[i] = As[kk][ty * 4 + i];
#pragma unroll
            for (int j = 0; j < 4; j++) b[j] = Bs[kk][tx * 4 + j];
#pragma unroll
            for (int i = 0; i < 4; i++)
#pragma unroll
                for (int j = 0; j < 4; j++) acc[i][j] += a[i] * b[j];
        }
        __syncthreads();
    }

#pragma unroll
    for (int i = 0; i < 4; i++) {
        const int m = bm + ty * 4 + i;     // m = b*1024 + s
        const int b = m >> 10;
        const int s = m & 1023;
#pragma unroll
        for (int j = 0; j < 4; j++) {
            const int n = bn + tx * 4 + j;
            out[(size_t)(s * 4 + b) * 256 + n] = acc[i][j] + bias[n];
        }
    }
}

// ---------------------------------------------------------------------------
extern "C" void kernel_launch(void* const* d_in, const int* in_sizes, int n_in,
                              void* d_out, int out_size)
{
    const unsigned char* mask = (const unsigned char*)d_in[6];
    const float* alpha = (const float*)d_in[15];
    const float* beta  = (const float*)d_in[16];
    float* out = (float*)d_out;

    cudaFuncSetAttribute(attn_fused_kernel,
                         cudaFuncAttributeMaxDynamicSharedMemorySize, FUSED_SMEM);

    // 0) zero exp-sum accumulators
    zero_sums_kernel<<<256, 256>>>();

    // 1) all six QKV projections in one launch (tf32 mma)
    ProjArgs pa;
    for (int i = 0; i < 6; i++) pa.x[i] = (const float*)d_in[i];
    pa.w[0] = (const float*)d_in[7];  pa.b[0] = (const float*)d_in[8];
    pa.w[1] = (const float*)d_in[11]; pa.b[1] = (const float*)d_in[12];
    proj_tf32_kernel<<<dim3(2, 32, 6), 256>>>(pa);

    // 2) exp-sum stats only (no score writes)
    sums_kernel<<<dim3(8, 8, 64), 256>>>(mask);

    // 3) fully fused: recompute scores + normalize + blend + prob write + P@V
    attn_fused_kernel<<<dim3(8, 32), 256, FUSED_SMEM>>>(out, mask, alpha, beta);

    // 4) both output projections in one launch (fp32)
    OutArgs oa;
    oa.w[0] = (const float*)d_in[9];  oa.b[0] = (const float*)d_in[10];
    oa.w[1] = (const float*)d_in[13]; oa.b[1] = (const float*)d_in[14];
    outproj_kernel<<<dim3(4, 64, 2), 256>>>(oa, out);
}

// round 10
// speedup vs baseline: 1.9493x; 1.0291x over previous
#include <cuda_runtime.h>
#include <cuda_bf16.h>
#include <math_constants.h>
#include <cstdint>

// Problem constants
#define SDIM 1024
#define BDIM 4
#define EDIM 256
#define HDIM 8
#define DDIM 32

// d_out layout: out_rgb [S,B,E], out_dpt [S,B,E], shared_rgb [B,H,S,S], shared_dpt [B,H,S,S]
#define OFF_OUT_RGB  0
#define OFF_OUT_DPT  (SDIM*BDIM*EDIM)              // 1048576
#define OFF_SHARED   (2*SDIM*BDIM*EDIM)            // 2097152
#define BHSS         ((size_t)BDIM*HDIM*SDIM*SDIM) // 33554432

#define SCALE 0.17677669529663687f   // 1/sqrt(32)

// Scratch
__device__ float g_qkv[6 * BDIM * HDIM * SDIM * DDIM];   // 25 MB
__device__ float g_ocat[2 * BDIM * SDIM * EDIM];         // 8 MB
__device__ float g_sums[2 * 32 * SDIM];                  // exp-sums per (st,bh,q)

// ---------------------------------------------------------------------------
// tf32 helpers (mma.sync m16n8k8, fp32 accum)
// ---------------------------------------------------------------------------
__device__ __forceinline__ uint32_t f2tf(float f) {
    uint32_t u;
    asm("cvt.rna.tf32.f32 %0, %1;" : "=r"(u) : "f"(f));
    return u;
}

__device__ __forceinline__ void mma_tf32(float* d, const uint32_t* a, const uint32_t* b) {
    asm volatile(
        "mma.sync.aligned.m16n8k8.row.col.f32.tf32.tf32.f32 "
        "{%0,%1,%2,%3}, {%4,%5,%6,%7}, {%8,%9}, {%0,%1,%2,%3};"
        : "+f"(d[0]), "+f"(d[1]), "+f"(d[2]), "+f"(d[3])
        : "r"(a[0]), "r"(a[1]), "r"(a[2]), "r"(a[3]),
          "r"(b[0]), "r"(b[1]));
}

// Convert a score C-fragment (16x8 tile: thread holds cols 2*tig, 2*tig+1 of
// rows gid, gid+8) into a PV A-fragment (thread needs cols tig, tig+4) via
// warp shuffles. No smem, no barrier.
__device__ __forceinline__ void c2a(uint32_t* av, float c0, float c1,
                                    float c2, float c3, int gid, int tig)
{
    const unsigned FULL = 0xffffffffu;
    const int base = gid * 4 + (tig >> 1);
    float x0 = __shfl_sync(FULL, c0, base);
    float x1 = __shfl_sync(FULL, c1, base);
    float y0 = __shfl_sync(FULL, c2, base);
    float y1 = __shfl_sync(FULL, c3, base);
    float z0 = __shfl_sync(FULL, c0, base + 2);
    float z1 = __shfl_sync(FULL, c1, base + 2);
    float w0 = __shfl_sync(FULL, c2, base + 2);
    float w1 = __shfl_sync(FULL, c3, base + 2);
    const bool odd = tig & 1;
    av[0] = f2tf(odd ? x1 : x0);
    av[1] = f2tf(odd ? y1 : y0);
    av[2] = f2tf(odd ? z1 : z0);
    av[3] = f2tf(odd ? w1 : w0);
}

__device__ __forceinline__ void stage4(uint32_t* dst, float4 v) {
    uint4 u = make_uint4(f2tf(v.x), f2tf(v.y), f2tf(v.z), f2tf(v.w));
    *reinterpret_cast<uint4*>(dst) = u;
}

// ---------------------------------------------------------------------------
// Kernel 0: zero the sums accumulator (graph-replayed every launch)
// ---------------------------------------------------------------------------
__global__ void zero_sums_kernel() {
    g_sums[blockIdx.x * 256 + threadIdx.x] = 0.f;
}

// ---------------------------------------------------------------------------
// Kernel 1: batched QKV projection via tf32 mma. grid.z = proj id 0..5.
// ---------------------------------------------------------------------------
struct ProjArgs {
    const float* x[6];
    const float* w[2];
    const float* b[2];
};

__global__ __launch_bounds__(256) void proj_tf32_kernel(ProjArgs args)
{
    __shared__ uint32_t As[128][36];
    __shared__ uint32_t Bs[128][36];
    const int proj = blockIdx.z;
    const int st = proj / 3;
    const int wsel = proj - st * 3;
    const float* x = args.x[proj];
    const float* W = args.w[st] + (size_t)wsel * 256 * 256;
    const float* bias = args.b[st] + wsel * 256;

    const int bm = blockIdx.y * 128;
    const int bn = blockIdx.x * 128;
    const int tid = threadIdx.x;
    const int wid = tid >> 5;
    const int lane = tid & 31;
    const int gid = lane >> 2;
    const int tig = lane & 3;
    const int wm = (wid & 3) * 32;
    const int wn = (wid >> 2) * 64;

    const int sr0 = tid >> 3;            // 0..31, +32*t
    const int sc0 = (tid & 7) * 4;       // 0,4,..28

    float4 pa[4], pb[4];
#pragma unroll
    for (int t = 0; t < 4; t++) {
        pa[t] = *reinterpret_cast<const float4*>(x + (size_t)(bm + sr0 + t * 32) * 256 + sc0);
        pb[t] = *reinterpret_cast<const float4*>(W + (size_t)(bn + sr0 + t * 32) * 256 + sc0);
    }

    float acc[2][8][4] = {};

    for (int kt = 0; kt < 8; kt++) {
#pragma unroll
        for (int t = 0; t < 4; t++) {
            const int r = sr0 + t * 32;
            As[r][sc0 + 0] = f2tf(pa[t].x); As[r][sc0 + 1] = f2tf(pa[t].y);
            As[r][sc0 + 2] = f2tf(pa[t].z); As[r][sc0 + 3] = f2tf(pa[t].w);
            Bs[r][sc0 + 0] = f2tf(pb[t].x); Bs[r][sc0 + 1] = f2tf(pb[t].y);
            Bs[r][sc0 + 2] = f2tf(pb[t].z); Bs[r][sc0 + 3] = f2tf(pb[t].w);
        }
        __syncthreads();

        if (kt < 7) {
            const int k0 = (kt + 1) * 32;
#pragma unroll
            for (int t = 0; t < 4; t++) {
                pa[t] = *reinterpret_cast<const float4*>(x + (size_t)(bm + sr0 + t * 32) * 256 + k0 + sc0);
                pb[t] = *reinterpret_cast<const float4*>(W + (size_t)(bn + sr0 + t * 32) * 256 + k0 + sc0);
            }
        }

#pragma unroll
        for (int kc = 0; kc < 4; kc++) {
            const int k8 = kc * 8;
            uint32_t a[2][4], b[8][2];
#pragma unroll
            for (int i = 0; i < 2; i++) {
                const int r = wm + i * 16;
                a[i][0] = As[r + gid][k8 + tig];
                a[i][1] = As[r + gid + 8][k8 + tig];
                a[i][2] = As[r + gid][k8 + tig + 4];
                a[i][3] = As[r + gid + 8][k8 + tig + 4];
            }
#pragma unroll
            for (int j = 0; j < 8; j++) {
                const int c = wn + j * 8;
                b[j][0] = Bs[c + gid][k8 + tig];
                b[j][1] = Bs[c + gid][k8 + tig + 4];
            }
#pragma unroll
            for (int i = 0; i < 2; i++)
#pragma unroll
                for (int j = 0; j < 8; j++)
                    mma_tf32(acc[i][j], a[i], b[j]);
        }
        __syncthreads();
    }

#pragma unroll
    for (int i = 0; i < 2; i++) {
        const int m0 = bm + wm + i * 16 + gid;
        const int s0 = m0 >> 2, b0 = m0 & 3;
        const int m1 = m0 + 8;
        const int s1 = m1 >> 2, b1 = m1 & 3;
#pragma unroll
        for (int j = 0; j < 8; j++) {
            const int c0 = bn + wn + j * 8 + tig * 2;
            const int h = c0 >> 5;
            const int d = c0 & 31;
            const float bv0 = bias[c0], bv1 = bias[c0 + 1];
            float* p0 = &g_qkv[(((size_t)(proj * 4 + b0) * 8 + h) * 1024 + s0) * 32 + d];
            float* p1 = &g_qkv[(((size_t)(proj * 4 + b1) * 8 + h) * 1024 + s1) * 32 + d];
            *reinterpret_cast<float2*>(p0) = make_float2(acc[i][j][0] + bv0, acc[i][j][1] + bv1);
            *reinterpret_cast<float2*>(p1) = make_float2(acc[i][j][2] + bv0, acc[i][j][3] + bv1);
        }
    }
}

// ---------------------------------------------------------------------------
// Kernel 2: exp-sum stats only (no score writes). QK^T via tf32 mma,
// per-row sum of exp(scaled score) with mask, atomicAdd into g_sums.
// Accumulation order matches attn_fused_kernel exactly -> identical values.
// ---------------------------------------------------------------------------
__global__ __launch_bounds__(256) void sums_kernel(const unsigned char* __restrict__ mask)
{
    __shared__ uint32_t Qs[128][36];
    __shared__ uint32_t Ks[128][36];
    const int z = blockIdx.z;
    const int st = z >> 5;
    const int bh = z & 31;
    const int bq = blockIdx.y * 128;
    const int bk = blockIdx.x * 128;

    const float* Q = g_qkv + ((size_t)(st * 3 + 0) * 32 + bh) * (SDIM * DDIM);
    const float* K = g_qkv + ((size_t)(st * 3 + 1) * 32 + bh) * (SDIM * DDIM);

    const int tid = threadIdx.x;
    for (int i = tid * 4; i < 128 * 32; i += 1024) {
        const int r = i >> 5, c = i & 31;
        float4 q4 = *reinterpret_cast<const float4*>(Q + (size_t)(bq + r) * 32 + c);
        float4 k4 = *reinterpret_cast<const float4*>(K + (size_t)(bk + r) * 32 + c);
        Qs[r][c + 0] = f2tf(q4.x); Qs[r][c + 1] = f2tf(q4.y);
        Qs[r][c + 2] = f2tf(q4.z); Qs[r][c + 3] = f2tf(q4.w);
        Ks[r][c + 0] = f2tf(k4.x); Ks[r][c + 1] = f2tf(k4.y);
        Ks[r][c + 2] = f2tf(k4.z); Ks[r][c + 3] = f2tf(k4.w);
    }
    __syncthreads();

    const int wid = tid >> 5;
    const int lane = tid & 31;
    const int gid = lane >> 2;
    const int tig = lane & 3;
    const int wm = (wid & 3) * 32;
    const int wn = (wid >> 2) * 64;

    float acc[2][8][4] = {};
#pragma unroll
    for (int kc = 0; kc < 4; kc++) {
        const int k0 = kc * 8;
        uint32_t a[2][4], b[8][2];
#pragma unroll
        for (int i = 0; i < 2; i++) {
            const int r = wm + i * 16;
            a[i][0] = Qs[r + gid][k0 + tig];
            a[i][1] = Qs[r + gid + 8][k0 + tig];
            a[i][2] = Qs[r + gid][k0 + tig + 4];
            a[i][3] = Qs[r + gid + 8][k0 + tig + 4];
        }
#pragma unroll
        for (int j = 0; j < 8; j++) {
            const int c = wn + j * 8;
            b[j][0] = Ks[c + gid][k0 + tig];
            b[j][1] = Ks[c + gid][k0 + tig + 4];
        }
#pragma unroll
        for (int i = 0; i < 2; i++)
#pragma unroll
            for (int j = 0; j < 8; j++)
                mma_tf32(acc[i][j], a[i], b[j]);
    }

    const unsigned char* mrow = mask + (size_t)(bh >> 3) * SDIM;
    float* sums = g_sums + (size_t)z * SDIM;
#pragma unroll
    for (int i = 0; i < 2; i++) {
        float slo = 0.f, shi = 0.f;
#pragma unroll
        for (int j = 0; j < 8; j++) {
            const int c0 = bk + wn + j * 8 + tig * 2;
            const float m0 = mrow[c0] ? 0.f : 1.f;
            const float m1 = mrow[c0 + 1] ? 0.f : 1.f;
            slo += m0 * __expf(acc[i][j][0] * SCALE) + m1 * __expf(acc[i][j][1] * SCALE);
            shi += m0 * __expf(acc[i][j][2] * SCALE) + m1 * __expf(acc[i][j][3] * SCALE);
        }
        slo += __shfl_xor_sync(0xffffffffu, slo, 1);
        slo += __shfl_xor_sync(0xffffffffu, slo, 2);
        shi += __shfl_xor_sync(0xffffffffu, shi, 1);
        shi += __shfl_xor_sync(0xffffffffu, shi, 2);
        if (tig == 0) {
            atomicAdd(&sums[bq + wm + i * 16 + gid], slo);
            atomicAdd(&sums[bq + wm + i * 16 + gid + 8], shi);
        }
    }
}

// ---------------------------------------------------------------------------
// Kernel 3 (FULLY FUSED, register-resident probs):
// recompute QK^T (tf32 mma) + exp/normalize/blend + single prob write (stcs)
// + shuffle C->A fragment + P@V (tf32 mma), all without a probs smem buffer.
// Block = one (b,h), 128 q rows, BOTH streams. 256 threads, 8 warps in m.
// k-tiles of 32 keys; K/V smem double-buffered (uint4 staging); ONE sync/tile.
// V rows padded to 40 words -> V fragment LDS are bank-conflict-free
// (bank = 8*tig + gid, all 32 lanes distinct). K rows stay at 36 (already
// conflict-free: bank = 4*gid + tig).
// ---------------------------------------------------------------------------
// smem layout (u32 indices):
#define KSOFF(st,buf)  (((st) * 2 + (buf)) * 1152)         // K tiles 2x2 x 32x36
#define VSOFF(st,buf)  (4608 + ((st) * 2 + (buf)) * 1280)  // V tiles 2x2 x 32x40
#define MSKOFF         9728                                // mask 1024 f32
#define FUSED_SMEM     (10752 * 4)                         // 43008 bytes

__global__ __launch_bounds__(256, 2) void attn_fused_kernel(
    float* __restrict__ dout, const unsigned char* __restrict__ mask,
    const float* __restrict__ alpha_p, const float* __restrict__ beta_p)
{
    extern __shared__ uint32_t sm[];
    float* msk = reinterpret_cast<float*>(sm + MSKOFF);
    const int bh = blockIdx.y;
    const int b = bh >> 3, h = bh & 7;
    const int bq = blockIdx.x * 128;

    const int tid = threadIdx.x;
    const int wid = tid >> 5;
    const int lane = tid & 31;
    const int gid = lane >> 2;
    const int tig = lane & 3;
    const int sr0 = tid >> 3;          // 0..31
    const int sc0 = (tid & 7) * 4;     // 0,4,..28
    const int r = wid * 16;            // warp q-row base (local)

    const float* Q1 = g_qkv + ((size_t)(0) * 32 + bh) * (SDIM * DDIM);
    const float* K1 = g_qkv + ((size_t)(1) * 32 + bh) * (SDIM * DDIM);
    const float* V1 = g_qkv + ((size_t)(2) * 32 + bh) * (SDIM * DDIM);
    const float* Q2 = g_qkv + ((size_t)(3) * 32 + bh) * (SDIM * DDIM);
    const float* K2 = g_qkv + ((size_t)(4) * 32 + bh) * (SDIM * DDIM);
    const float* V2 = g_qkv + ((size_t)(5) * 32 + bh) * (SDIM * DDIM);
    float* S1 = dout + OFF_SHARED + ((size_t)bh * SDIM + bq) * SDIM;
    float* S2 = S1 + BHSS;

    // mask multiplier table
    for (int i = tid; i < SDIM; i += 256)
        msk[i] = mask[(size_t)b * SDIM + i] ? 0.f : 1.f;

    // Q fragments straight from gmem (one-time prologue)
    uint32_t qf[2][4][4];
#pragma unroll
    for (int st = 0; st < 2; st++) {
        const float* Q = st ? Q2 : Q1;
#pragma unroll
        for (int ks = 0; ks < 4; ks++) {
            qf[st][ks][0] = f2tf(Q[(size_t)(bq + r + gid) * 32 + 8 * ks + tig]);
            qf[st][ks][1] = f2tf(Q[(size_t)(bq + r + gid + 8) * 32 + 8 * ks + tig]);
            qf[st][ks][2] = f2tf(Q[(size_t)(bq + r + gid) * 32 + 8 * ks + tig + 4]);
            qf[st][ks][3] = f2tf(Q[(size_t)(bq + r + gid + 8) * 32 + 8 * ks + tig + 4]);
        }
    }

    // blend coefficients folded with inverse sums (per thread's 2 rows)
    const float a = *alpha_p, bt = *beta_p;
    const int q0 = bq + r + gid;
    const float i1lo = 1.f / g_sums[(size_t)bh * SDIM + q0];
    const float i1hi = 1.f / g_sums[(size_t)bh * SDIM + q0 + 8];
    const float i2lo = 1.f / g_sums[(size_t)(32 + bh) * SDIM + q0];
    const float i2hi = 1.f / g_sums[(size_t)(32 + bh) * SDIM + q0 + 8];
    const float c1lo = (1.f - a) * i1lo, c2lo = a * i2lo;
    const float c1hi = (1.f - a) * i1hi, c2hi = a * i2hi;
    const float d2lo = (1.f - bt) * i2lo, d1lo = bt * i1lo;
    const float d2hi = (1.f - bt) * i2hi, d1hi = bt * i1hi;

    // stage K/V tile 0 into buffer 0 (vectorized)
    stage4(sm + KSOFF(0, 0) + sr0 * 36 + sc0,
           *reinterpret_cast<const float4*>(K1 + (size_t)sr0 * 32 + sc0));
    stage4(sm + KSOFF(1, 0) + sr0 * 36 + sc0,
           *reinterpret_cast<const float4*>(K2 + (size_t)sr0 * 32 + sc0));
    stage4(sm + VSOFF(0, 0) + sr0 * 40 + sc0,
           *reinterpret_cast<const float4*>(V1 + (size_t)sr0 * 32 + sc0));
    stage4(sm + VSOFF(1, 0) + sr0 * 40 + sc0,
           *reinterpret_cast<const float4*>(V2 + (size_t)sr0 * 32 + sc0));
    __syncthreads();

    float o[2][4][4] = {};

    for (int kt = 0; kt < 32; kt++) {
        const int cur = kt & 1;

        // prefetch next K/V tiles into registers
        float4 k1n, k2n, v1n, v2n;
        if (kt < 31) {
            const int k0 = (kt + 1) * 32;
            k1n = *reinterpret_cast<const float4*>(K1 + (size_t)(k0 + sr0) * 32 + sc0);
            k2n = *reinterpret_cast<const float4*>(K2 + (size_t)(k0 + sr0) * 32 + sc0);
            v1n = *reinterpret_cast<const float4*>(V1 + (size_t)(k0 + sr0) * 32 + sc0);
            v2n = *reinterpret_cast<const float4*>(V2 + (size_t)(k0 + sr0) * 32 + sc0);
        }

        const uint32_t* KA = sm + KSOFF(0, cur);
        const uint32_t* KB = sm + KSOFF(1, cur);
        const uint32_t* VA = sm + VSOFF(0, cur);
        const uint32_t* VB = sm + VSOFF(1, cur);

        // ---- per 8-key group: scores -> probs -> shuffle -> PV mma ----
#pragma unroll
        for (int j = 0; j < 4; j++) {
            float sA[4] = {}, sB[4] = {};
#pragma unroll
            for (int ks = 0; ks < 4; ks++) {
                uint32_t bf[2];
                bf[0] = KA[(j * 8 + gid) * 36 + 8 * ks + tig];
                bf[1] = KA[(j * 8 + gid) * 36 + 8 * ks + tig + 4];
                mma_tf32(sA, qf[0][ks], bf);
                bf[0] = KB[(j * 8 + gid) * 36 + 8 * ks + tig];
                bf[1] = KB[(j * 8 + gid) * 36 + 8 * ks + tig + 4];
                mma_tf32(sB, qf[1][ks], bf);
            }
            const int c0 = kt * 32 + j * 8 + tig * 2;
            const float m0 = msk[c0], m1 = msk[c0 + 1];
            const float e1x = m0 * __expf(sA[0] * SCALE), e1y = m1 * __expf(sA[1] * SCALE);
            const float e1z = m0 * __expf(sA[2] * SCALE), e1w = m1 * __expf(sA[3] * SCALE);
            const float e2x = m0 * __expf(sB[0] * SCALE), e2y = m1 * __expf(sB[1] * SCALE);
            const float e2z = m0 * __expf(sB[2] * SCALE), e2w = m1 * __expf(sB[3] * SCALE);
            const float p1x = c1lo * e1x + c2lo * e2x, p1y = c1lo * e1y + c2lo * e2y;
            const float p1z = c1hi * e1z + c2hi * e2z, p1w = c1hi * e1w + c2hi * e2w;
            const float p2x = d2lo * e2x + d1lo * e1x, p2y = d2lo * e2y + d1lo * e1y;
            const float p2z = d2hi * e2z + d1hi * e1z, p2w = d2hi * e2w + d1hi * e1w;
            // single DRAM write of the blended probs
            __stcs(reinterpret_cast<float2*>(S1 + (size_t)(r + gid) * SDIM + c0), make_float2(p1x, p1y));
            __stcs(reinterpret_cast<float2*>(S1 + (size_t)(r + gid + 8) * SDIM + c0), make_float2(p1z, p1w));
            __stcs(reinterpret_cast<float2*>(S2 + (size_t)(r + gid) * SDIM + c0), make_float2(p2x, p2y));
            __stcs(reinterpret_cast<float2*>(S2 + (size_t)(r + gid + 8) * SDIM + c0), make_float2(p2z, p2w));

            // C-fragment -> A-fragment in registers, then PV mma right away
            uint32_t avA[4], avB[4];
            c2a(avA, p1x, p1y, p1z, p1w, gid, tig);
            c2a(avB, p2x, p2y, p2z, p2w, gid, tig);
#pragma unroll
            for (int j2 = 0; j2 < 4; j2++) {
                uint32_t bf[2];
                bf[0] = VA[(j * 8 + tig) * 40 + j2 * 8 + gid];
                bf[1] = VA[(j * 8 + tig + 4) * 40 + j2 * 8 + gid];
                mma_tf32(o[0][j2], avA, bf);
                bf[0] = VB[(j * 8 + tig) * 40 + j2 * 8 + gid];
                bf[1] = VB[(j * 8 + tig + 4) * 40 + j2 * 8 + gid];
                mma_tf32(o[1][j2], avB, bf);
            }
        }

        // stash prefetched K/V into the other buffer (vectorized)
        if (kt < 31) {
            stage4(sm + KSOFF(0, cur ^ 1) + sr0 * 36 + sc0, k1n);
            stage4(sm + KSOFF(1, cur ^ 1) + sr0 * 36 + sc0, k2n);
            stage4(sm + VSOFF(0, cur ^ 1) + sr0 * 40 + sc0, v1n);
            stage4(sm + VSOFF(1, cur ^ 1) + sr0 * 40 + sc0, v2n);
        }
        __syncthreads();
    }

    // epilogue: O -> g_ocat
#pragma unroll
    for (int st = 0; st < 2; st++) {
#pragma unroll
        for (int j2 = 0; j2 < 4; j2++) {
            const int d0 = j2 * 8 + tig * 2;
            float* o0 = &g_ocat[((size_t)(st * 4 + b) * SDIM + q0) * EDIM + h * 32 + d0];
            float* o1 = &g_ocat[((size_t)(st * 4 + b) * SDIM + q0 + 8) * EDIM + h * 32 + d0];
            *reinterpret_cast<float2*>(o0) = make_float2(o[st][j2][0], o[st][j2][1]);
            *reinterpret_cast<float2*>(o1) = make_float2(o[st][j2][2], o[st][j2][3]);
        }
    }
}

// ---------------------------------------------------------------------------
// Kernel 4: batched output projection (fp32, accuracy headroom). grid.z = st.
// ---------------------------------------------------------------------------
struct OutArgs {
    const float* w[2];
    const float* b[2];
};

__global__ __launch_bounds__(256) void outproj_kernel(OutArgs args, float* __restrict__ dout)
{
    __shared__ float As[16][64];
    __shared__ float Bs[16][64];
    const int st = blockIdx.z;
    const float* W = args.w[st];
    const float* bias = args.b[st];
    float* out = dout + (size_t)st * (SDIM * BDIM * EDIM);

    const int bm = blockIdx.y * 64;
    const int bn = blockIdx.x * 64;
    const int tid = threadIdx.x;
    const int tx = tid & 15;
    const int ty = tid >> 4;
    const float* A = g_ocat + (size_t)st * (BDIM * SDIM * EDIM);

    float acc[4][4] = {};
    const int lrow = tid >> 2;
    const int lcol = (tid & 3) * 4;

    for (int k0 = 0; k0 < 256; k0 += 16) {
        float4 va = *reinterpret_cast<const float4*>(A + (size_t)(bm + lrow) * 256 + k0 + lcol);
        float4 vb = *reinterpret_cast<const float4*>(W + (size_t)(bn + lrow) * 256 + k0 + lcol);
        As[lcol + 0][lrow] = va.x; As[lcol + 1][lrow] = va.y;
        As[lcol + 2][lrow] = va.z; As[lcol + 3][lrow] = va.w;
        Bs[lcol + 0][lrow] = vb.x; Bs[lcol + 1][lrow] = vb.y;
        Bs[lcol + 2][lrow] = vb.z; Bs[lcol + 3][lrow] = vb.w;
        __syncthreads();
#pragma unroll
        for (int kk = 0; kk < 16; kk++) {
            float a[4], b[4];
#pragma unroll
            for (int i = 0; i < 4; i++) a[i] = As[kk][ty * 4 + i];
#pragma unroll
            for (int j = 0; j < 4; j++) b[j] = Bs[kk][tx * 4 + j];
#pragma unroll
            for (int i = 0; i < 4; i++)
#pragma unroll
                for (int j = 0; j < 4; j++) acc[i][j] += a[i] * b[j];
        }
        __syncthreads();
    }

#pragma unroll
    for (int i = 0; i < 4; i++) {
        const int m = bm + ty * 4 + i;     // m = b*1024 + s
        const int b = m >> 10;
        const int s = m & 1023;
#pragma unroll
        for (int j = 0; j < 4; j++) {
            const int n = bn + tx * 4 + j;
            out[(size_t)(s * 4 + b) * 256 + n] = acc[i][j] + bias[n];
        }
    }
}

// ---------------------------------------------------------------------------
extern "C" void kernel_launch(void* const* d_in, const int* in_sizes, int n_in,
                              void* d_out, int out_size)
{
    const unsigned char* mask = (const unsigned char*)d_in[6];
    const float* alpha = (const float*)d_in[15];
    const float* beta  = (const float*)d_in[16];
    float* out = (float*)d_out;

    cudaFuncSetAttribute(attn_fused_kernel,
                         cudaFuncAttributeMaxDynamicSharedMemorySize, FUSED_SMEM);

    // 0) zero exp-sum accumulators
    zero_sums_kernel<<<256, 256>>>();

    // 1) all six QKV projections in one launch (tf32 mma)
    ProjArgs pa;
    for (int i = 0; i < 6; i++) pa.x[i] = (const float*)d_in[i];
    pa.w[0] = (const float*)d_in[7];  pa.b[0] = (const float*)d_in[8];
    pa.w[1] = (const float*)d_in[11]; pa.b[1] = (const float*)d_in[12];
    proj_tf32_kernel<<<dim3(2, 32, 6), 256>>>(pa);

    // 2) exp-sum stats only (no score writes)
    sums_kernel<<<dim3(8, 8, 64), 256>>>(mask);

    // 3) fully fused: recompute scores + normalize + blend + prob write + P@V
    attn_fused_kernel<<<dim3(8, 32), 256, FUSED_SMEM>>>(out, mask, alpha, beta);

    // 4) both output projections in one launch (fp32)
    OutArgs oa;
    oa.w[0] = (const float*)d_in[9];  oa.b[0] = (const float*)d_in[10];
    oa.w[1] = (const float*)d_in[13]; oa.b[1] = (const float*)d_in[14];
    outproj_kernel<<<dim3(4, 64, 2), 256>>>(oa, out);
}